// round 13
// baseline (speedup 1.0000x reference)
#include <cuda_runtime.h>
#include <math.h>

#define IMG_H 512
#define IMG_W 512
#define NB    8
#define NC    3
#define HID   64
#define NPIX  (IMG_H*IMG_W)
#define KTOP  26214
#define OUT_XOUT (NB*NC*NPIX)
#define PLANE NPIX
#define BSTRIDE (NC*NPIX)

#define TW 32
#define TH 16
#define HS_W 34           /* valid h cols */
#define HSTR 36           /* h row stride */
#define HROWS 18
#define HPLANE 652        /* 652 % 32 == 12 (4*odd) -> conflict-free lane-strided STS.128; mult of 4 -> aligned */

/* blob layout (floats) */
#define OFF_W1 0          /* [27 tap][64 oc]                     1728 */
#define OFF_W2 1728       /* [64 ic][9 tap][3 out x dup2]        3456 */
#define OFF_B1 5184       /* 64 */
#define OFF_B2 5248       /* 4  */
#define OFF_CW 5252       /* 12 */
#define OFF_CB 5264       /* 4  */
#define BLOB_FLOATS 5268
/* smem layout */
#define SM_COL 5268       /* 4 */
#define SM_XD  5272       /* duplicated x pairs: 3*20*36*2 = 4320 */
#define SM_H   9592       /* 64*652 = 41728 (conv2 partials alias this after sync) */
#define SMEM_FLOATS 51320
#define SMEM_BYTES (SMEM_FLOATS*4)

typedef unsigned long long ull;

__device__ float    g_blob[BLOB_FLOATS];
__device__ float    g_pmean[24*8];
__device__ float    g_color[24];
__device__ float    g_m[NB*NPIX];
__device__ float    g_bright[NB*NPIX];
__device__ unsigned g_hist[4][NB][256];
__device__ unsigned g_prefix[NB];
__device__ unsigned g_remk[NB];
__device__ float    g_gt[NB][64][3];
__device__ unsigned g_eqcB[NB][64];
__device__ float    g_eqsB[NB][64][3];

__device__ __forceinline__ ull pk2(float a, float b) {
    ull r; asm("mov.b64 %0,{%1,%2};" : "=l"(r) : "f"(a), "f"(b)); return r;
}
__device__ __forceinline__ ull pkd(float a) { return pk2(a, a); }
__device__ __forceinline__ void upk(ull v, float& lo, float& hi) {
    asm("mov.b64 {%0,%1},%2;" : "=f"(lo), "=f"(hi) : "l"(v));
}
__device__ __forceinline__ ull f2(ull a, ull b, ull c) {
    ull d; asm("fma.rn.f32x2 %0,%1,%2,%3;" : "=l"(d) : "l"(a), "l"(b), "l"(c)); return d;
}
__device__ __forceinline__ float sigm(float v) { return 1.f / (1.f + expf(-v)); }

/* ---------------- prep ---------------- */
__global__ void prep_kernel(const float* __restrict__ w1, const float* __restrict__ b1,
                            const float* __restrict__ w2, const float* __restrict__ b2,
                            const float* __restrict__ cw, const float* __restrict__ cb) {
    int tid = threadIdx.x;
    for (int i = tid; i < 1728; i += 256) {           /* w1: [oc][27] -> [tap][oc] */
        int t = i >> 6, oc = i & 63;
        g_blob[OFF_W1 + t*64 + oc] = w1[oc*27 + t];
    }
    for (int i = tid; i < 3456; i += 256) {           /* w2: [oc][ic][9] -> [ic][tap][o dup2] */
        int ic = i / 54, r = i % 54, t = r / 6, o = (r % 6) >> 1;
        g_blob[OFF_W2 + i] = w2[o*576 + ic*9 + t];
    }
    for (int i = tid; i < 64; i += 256) g_blob[OFF_B1 + i] = b1[i];
    if (tid < 4)  g_blob[OFF_B2 + tid] = (tid < 3) ? b2[tid] : 0.f;
    if (tid < 12) g_blob[OFF_CW + tid] = cw[tid];
    if (tid < 4)  g_blob[OFF_CB + tid] = cb[tid];
    unsigned* hz = &g_hist[0][0][0];
    for (int i = tid; i < 4*NB*256; i += 256) hz[i] = 0u;
    if (tid < NB) { g_prefix[tid] = 0u; g_remk[tid] = KTOP; }
}

/* ---------------- mean / color ---------------- */
__device__ float block_reduce256(float v, float* sbuf) {
    int tid = threadIdx.x;
    sbuf[tid] = v; __syncthreads();
    for (int s = 128; s > 0; s >>= 1) {
        if (tid < s) sbuf[tid] += sbuf[tid + s];
        __syncthreads();
    }
    float r = sbuf[0]; __syncthreads();
    return r;
}

__global__ void meanA_kernel(const float* __restrict__ x) {
    __shared__ float sbuf[256];
    int chunk = blockIdx.x, bc = blockIdx.y, tid = threadIdx.x;
    int base = bc * NPIX + chunk * 32768;
    float s = 0.f;
    for (int i = tid; i < 32768; i += 256) s += x[base + i];
    float r = block_reduce256(s, sbuf);
    if (tid == 0) g_pmean[bc*8 + chunk] = r;
}

__global__ void meanB_kernel(const float* __restrict__ color_w, const float* __restrict__ color_b) {
    __shared__ float mm[24];
    int tid = threadIdx.x;
    if (tid < 24) {
        float s = 0.f;
        for (int j = 0; j < 8; j++) s += g_pmean[tid*8 + j];
        mm[tid] = s * (1.f / (float)NPIX);
    }
    __syncthreads();
    if (tid < 24) {
        int b = tid / 3, c = tid % 3;
        float lin = color_b[c];
        for (int j = 0; j < 3; j++) lin += mm[b*3 + j] * color_w[c*3 + j];
        g_color[tid] = sigm(lin);
    }
}

/* ---------------- main fused kernel: 512 threads, 1 block/SM ---------------- */
__global__ void __launch_bounds__(512, 1)
main_kernel(const float* __restrict__ x, float* __restrict__ out) {
    extern __shared__ float sm[];
    int tid = threadIdx.x;
    int b  = blockIdx.z;
    int r0 = blockIdx.y * TH;
    int c0 = blockIdx.x * TW;

    for (int i = tid; i < BLOB_FLOATS; i += 512) sm[i] = g_blob[i];
    if (tid < 3) sm[SM_COL + tid] = g_color[b*3 + tid];

    /* x tile duplicated as (v,v) pairs: 3 x 20 x 36, origin (r0-2, c0-2) */
    for (int i = tid; i < 3*20*36; i += 512) {
        int ci = i / 720;
        int rr = (i % 720) / 36;
        int cc = i % 36;
        int gr = r0 - 2 + rr, gc = c0 - 2 + cc;
        float v = 0.f;
        if ((unsigned)gr < 512u && (unsigned)gc < 512u)
            v = x[b*BSTRIDE + ci*PLANE + gr*512 + gc];
        *(ull*)&sm[SM_XD + 2*i] = pkd(v);
    }
    __syncthreads();

    /* ---- conv1: warp-per-quad, weights in registers, dup-x (no packs) ----
       lane owns oc pair (lane, lane+32) -> lane-stride HPLANE -> conflict-free STS.128.
       warp w handles quads w, w+16, ... (162 quads total). */
    {
        int warp = tid >> 5, lane = tid & 31;
        ull w[27];
        #pragma unroll
        for (int t = 0; t < 27; t++)
            w[t] = pk2(sm[OFF_W1 + t*64 + lane], sm[OFF_W1 + t*64 + lane + 32]);
        ull bias = pk2(sm[OFF_B1 + lane], sm[OFF_B1 + lane + 32]);

        for (int quad = warp; quad < 162; quad += 16) {
            int pr = quad / 9, pc0 = (quad % 9) << 2;
            ull acc0 = bias, acc1 = bias, acc2 = bias, acc3 = bias;
            #pragma unroll
            for (int ci = 0; ci < 3; ci++) {
                #pragma unroll
                for (int dr = 0; dr < 3; dr++) {
                    const ull* xrow = (const ull*)&sm[SM_XD + (ci*720 + (pr+dr)*36 + pc0)*2];
                    ull x0 = xrow[0], x1 = xrow[1], x2 = xrow[2];
                    ull x3 = xrow[3], x4 = xrow[4], x5 = xrow[5];
                    const int tb = ci*9 + dr*3;
                    acc0 = f2(x0, w[tb+0], acc0); acc1 = f2(x1, w[tb+0], acc1);
                    acc2 = f2(x2, w[tb+0], acc2); acc3 = f2(x3, w[tb+0], acc3);
                    acc0 = f2(x1, w[tb+1], acc0); acc1 = f2(x2, w[tb+1], acc1);
                    acc2 = f2(x3, w[tb+1], acc2); acc3 = f2(x4, w[tb+1], acc3);
                    acc0 = f2(x2, w[tb+2], acc0); acc1 = f2(x3, w[tb+2], acc1);
                    acc2 = f2(x4, w[tb+2], acc2); acc3 = f2(x5, w[tb+2], acc3);
                }
            }
            int gr = r0 - 1 + pr;
            bool rok = ((unsigned)gr < 512u);
            float f[4][2];
            upk(acc0, f[0][0], f[0][1]); upk(acc1, f[1][0], f[1][1]);
            upk(acc2, f[2][0], f[2][1]); upk(acc3, f[3][0], f[3][1]);
            float4 v0, v1;
            float* pv0 = (float*)&v0;
            float* pv1 = (float*)&v1;
            #pragma unroll
            for (int j = 0; j < 4; j++) {
                int pc = pc0 + j;
                bool ok = rok && (pc < HS_W) && ((unsigned)(c0 - 1 + pc) < 512u);
                pv0[j] = ok ? fmaxf(f[j][0], 0.f) : 0.f;
                pv1[j] = ok ? fmaxf(f[j][1], 0.f) : 0.f;
            }
            *(float4*)&sm[SM_H + lane*HPLANE + pr*HSTR + pc0]        = v0;
            *(float4*)&sm[SM_H + (lane+32)*HPLANE + pr*HSTR + pc0]   = v1;
        }
    }
    __syncthreads();

    /* ---- conv2: unit = 8 pixels (4 pairs) x 3 outs x 8 input channels ---- */
    ull a[4][3];
    int icg = tid >> 6;            /* 0..7 */
    int oct = tid & 63;            /* 0..63 */
    {
        int py  = oct >> 2;
        int px0 = (oct & 3) << 3;
        #pragma unroll
        for (int p = 0; p < 4; p++) { a[p][0] = 0ull; a[p][1] = 0ull; a[p][2] = 0ull; }

        int ic0 = icg * 8;
        for (int ic = ic0; ic < ic0 + 8; ic++) {
            const float* hb = &sm[SM_H + ic*HPLANE + py*HSTR + px0];
            const float* wb = &sm[OFF_W2 + ic*54];
            #pragma unroll
            for (int dr = 0; dr < 3; dr++) {
                float4 h0 = *(const float4*)&hb[dr*HSTR];
                float4 h1 = *(const float4*)&hb[dr*HSTR + 4];
                float2 h2 = *(const float2*)&hb[dr*HSTR + 8];
                ull p01 = pk2(h0.x, h0.y), p23 = pk2(h0.z, h0.w);
                ull p45 = pk2(h1.x, h1.y), p67 = pk2(h1.z, h1.w);
                ull p89 = pk2(h2.x, h2.y);
                ull p12 = pk2(h0.y, h0.z), p34 = pk2(h0.w, h1.x);
                ull p56 = pk2(h1.y, h1.z), p78 = pk2(h1.w, h2.x);
                const ull* wp0 = (const ull*)&wb[(dr*3 + 0)*6];
                const ull* wp1 = (const ull*)&wb[(dr*3 + 1)*6];
                const ull* wp2 = (const ull*)&wb[(dr*3 + 2)*6];
                {
                    ull w0 = wp0[0], w1 = wp0[1], w2 = wp0[2];
                    a[0][0]=f2(p01,w0,a[0][0]); a[0][1]=f2(p01,w1,a[0][1]); a[0][2]=f2(p01,w2,a[0][2]);
                    a[1][0]=f2(p23,w0,a[1][0]); a[1][1]=f2(p23,w1,a[1][1]); a[1][2]=f2(p23,w2,a[1][2]);
                    a[2][0]=f2(p45,w0,a[2][0]); a[2][1]=f2(p45,w1,a[2][1]); a[2][2]=f2(p45,w2,a[2][2]);
                    a[3][0]=f2(p67,w0,a[3][0]); a[3][1]=f2(p67,w1,a[3][1]); a[3][2]=f2(p67,w2,a[3][2]);
                }
                {
                    ull w0 = wp1[0], w1 = wp1[1], w2 = wp1[2];
                    a[0][0]=f2(p12,w0,a[0][0]); a[0][1]=f2(p12,w1,a[0][1]); a[0][2]=f2(p12,w2,a[0][2]);
                    a[1][0]=f2(p34,w0,a[1][0]); a[1][1]=f2(p34,w1,a[1][1]); a[1][2]=f2(p34,w2,a[1][2]);
                    a[2][0]=f2(p56,w0,a[2][0]); a[2][1]=f2(p56,w1,a[2][1]); a[2][2]=f2(p56,w2,a[2][2]);
                    a[3][0]=f2(p78,w0,a[3][0]); a[3][1]=f2(p78,w1,a[3][1]); a[3][2]=f2(p78,w2,a[3][2]);
                }
                {
                    ull w0 = wp2[0], w1 = wp2[1], w2 = wp2[2];
                    a[0][0]=f2(p23,w0,a[0][0]); a[0][1]=f2(p23,w1,a[0][1]); a[0][2]=f2(p23,w2,a[0][2]);
                    a[1][0]=f2(p45,w0,a[1][0]); a[1][1]=f2(p45,w1,a[1][1]); a[1][2]=f2(p45,w2,a[1][2]);
                    a[2][0]=f2(p67,w0,a[2][0]); a[2][1]=f2(p67,w1,a[2][1]); a[2][2]=f2(p67,w2,a[2][2]);
                    a[3][0]=f2(p89,w0,a[3][0]); a[3][1]=f2(p89,w1,a[3][1]); a[3][2]=f2(p89,w2,a[3][2]);
                }
            }
        }
    }
    __syncthreads();   /* all H reads done; RED aliases H region */
    {
        float* rp = &sm[SM_H + (oct*8 + icg)*24];
        #pragma unroll
        for (int o = 0; o < 3; o++) {
            #pragma unroll
            for (int p = 0; p < 4; p++) {
                float lo, hi; upk(a[p][o], lo, hi);
                rp[o*8 + 2*p]     = lo;
                rp[o*8 + 2*p + 1] = hi;
            }
        }
    }
    __syncthreads();

    /* ---- finalize: sum partials, sigmoid + color + 1x1 + x_out ---- */
    {
        int py = tid >> 5, px = tid & 31;
        int o8 = py*4 + (px >> 3), jj = px & 7;
        float s0 = sm[OFF_B2], s1 = sm[OFF_B2+1], s2 = sm[OFF_B2+2];
        #pragma unroll
        for (int g = 0; g < 8; g++) {
            const float* rp = &sm[SM_H + (o8*8 + g)*24];
            s0 += rp[jj]; s1 += rp[8 + jj]; s2 += rp[16 + jj];
        }
        float ih0 = sigm(s0) * sm[SM_COL + 0];
        float ih1 = sigm(s1) * sm[SM_COL + 1];
        float ih2 = sigm(s2) * sm[SM_COL + 2];
        const float* cw = &sm[OFF_CW];
        const float* cb = &sm[OFF_CB];
        float K = cb[0] + cw[0]*ih0 + cw[1]*ih1 + cw[2]*ih2;
        int pix = (r0 + py)*512 + (c0 + px);
        float mx = -1e30f;
        #pragma unroll
        for (int c = 0; c < 3; c++) {
            float Bt = cb[1+c] + cw[(1+c)*3+0]*ih0 + cw[(1+c)*3+1]*ih1 + cw[(1+c)*3+2]*ih2;
            float xv = sm[SM_XD + (c*720 + (py+2)*36 + (px+2))*2];
            float xo = K*xv - Bt + xv;
            out[b*BSTRIDE + c*PLANE + pix] = xo;
            mx = fmaxf(mx, xo);
        }
        g_m[b*NPIX + pix] = mx;
    }
}

/* ---------------- bright (reflect pad, 3x3) + fused radix pass-0 hist ---------------- */
__global__ void brighthist_kernel() {
    __shared__ unsigned h[256];
    int b = blockIdx.y, tid = threadIdx.x;
    h[tid] = 0; __syncthreads();
    const float* m = &g_m[b*NPIX];
    int base = blockIdx.x*2048;
    #pragma unroll
    for (int k = 0; k < 8; k++) {
        int p = base + k*256 + tid;
        int r = p >> 9, c = p & 511;
        float acc = 0.f;
        #pragma unroll
        for (int dr = 0; dr < 3; dr++) {
            int rr = r + dr - 1; rr = rr < 0 ? 1 : (rr > 511 ? 510 : rr);
            #pragma unroll
            for (int dc = 0; dc < 3; dc++) {
                int cc = c + dc - 1; cc = cc < 0 ? 1 : (cc > 511 ? 510 : cc);
                float w = (dr == 1 && dc == 1) ? 1.0f : (1.f/9.f);
                acc += w * m[rr*512 + cc];
            }
        }
        float bv = fmaxf(acc, 0.f);
        g_bright[b*NPIX + p] = bv;
        atomicAdd(&h[__float_as_uint(bv) >> 24], 1u);
    }
    __syncthreads();
    if (h[tid]) atomicAdd(&g_hist[0][b][tid], h[tid]);
}

/* ---------------- radix select (passes 1-3) ---------------- */
__global__ void hist_kernel(int pass) {
    __shared__ unsigned h[256];
    int b = blockIdx.y, tid = threadIdx.x;
    h[tid] = 0; __syncthreads();
    unsigned pref = g_prefix[b];
    int shift = 24 - 8*pass;
    int base = b*NPIX + blockIdx.x*1024;
    for (int i = tid; i < 1024; i += 256) {
        unsigned u = __float_as_uint(g_bright[base + i]);
        if ((u >> (shift + 8)) == pref) atomicAdd(&h[(u >> shift) & 255], 1u);
    }
    __syncthreads();
    if (h[tid]) atomicAdd(&g_hist[pass][b][tid], h[tid]);
}

__global__ void scan_kernel(int pass) {
    int b = blockIdx.x;
    if (threadIdx.x == 0) {
        unsigned remk = g_remk[b], cum = 0, pref = g_prefix[b], sel = 0;
        for (int bin = 255; bin >= 0; bin--) {
            unsigned c = g_hist[pass][b][bin];
            if (cum + c >= remk) { sel = (unsigned)bin; break; }
            cum += c;
        }
        g_prefix[b] = (pref << 8) | sel;
        g_remk[b] = remk - cum;
    }
}

__global__ void sel1_kernel(const float* __restrict__ outp) {
    __shared__ float s0[256], s1[256], s2[256];
    __shared__ unsigned sc[256];
    int b = blockIdx.y, blk = blockIdx.x, tid = threadIdx.x;
    unsigned T = g_prefix[b];
    const float* br  = &g_bright[b*NPIX];
    const float* img = outp + b*BSTRIDE;
    int base = blk*4096;
    float a0 = 0, a1 = 0, a2 = 0; unsigned ec = 0;
    for (int i = tid; i < 4096; i += 256) {
        int p = base + i;
        unsigned u = __float_as_uint(br[p]);
        if (u > T) { a0 += img[p*3]; a1 += img[p*3+1]; a2 += img[p*3+2]; }
        else if (u == T) ec++;
    }
    s0[tid]=a0; s1[tid]=a1; s2[tid]=a2; sc[tid]=ec; __syncthreads();
    for (int s = 128; s > 0; s >>= 1) {
        if (tid < s) { s0[tid]+=s0[tid+s]; s1[tid]+=s1[tid+s]; s2[tid]+=s2[tid+s]; sc[tid]+=sc[tid+s]; }
        __syncthreads();
    }
    if (tid == 0) {
        g_gt[b][blk][0]=s0[0]; g_gt[b][blk][1]=s1[0]; g_gt[b][blk][2]=s2[0];
        g_eqcB[b][blk]=sc[0];
    }
}

__global__ void sel3_kernel(const float* __restrict__ outp) {
    __shared__ unsigned scnt[256];
    __shared__ unsigned eqc[64];
    __shared__ unsigned startsh;
    __shared__ float s0[256], s1[256], s2[256];
    int b = blockIdx.y, blk = blockIdx.x, tid = threadIdx.x;
    unsigned T = g_prefix[b], remk = g_remk[b];
    const float* br  = &g_bright[b*NPIX];
    const float* img = outp + b*BSTRIDE;
    if (tid < 64) eqc[tid] = g_eqcB[b][tid];
    int start = blk*4096 + tid*16;
    unsigned cnt = 0;
    for (int j = 0; j < 16; j++) if (__float_as_uint(br[start+j]) == T) cnt++;
    scnt[tid] = cnt; __syncthreads();
    if (tid == 0) {
        unsigned run = 0;
        for (int i = 0; i < blk; i++) run += eqc[i];
        startsh = run;
        run = 0;
        for (int i = 0; i < 256; i++) { unsigned c = scnt[i]; scnt[i] = run; run += c; }
    }
    __syncthreads();
    unsigned rank = startsh + scnt[tid];
    float a0 = 0, a1 = 0, a2 = 0;
    for (int j = 0; j < 16; j++) {
        int p = start + j;
        if (__float_as_uint(br[p]) == T) {
            if (rank < remk) { a0 += img[p*3]; a1 += img[p*3+1]; a2 += img[p*3+2]; }
            rank++;
        }
    }
    s0[tid]=a0; s1[tid]=a1; s2[tid]=a2; __syncthreads();
    for (int s = 128; s > 0; s >>= 1) {
        if (tid < s) { s0[tid]+=s0[tid+s]; s1[tid]+=s1[tid+s]; s2[tid]+=s2[tid+s]; }
        __syncthreads();
    }
    if (tid == 0) { g_eqsB[b][blk][0]=s0[0]; g_eqsB[b][blk][1]=s1[0]; g_eqsB[b][blk][2]=s2[0]; }
}

__global__ void sel4_kernel(float* __restrict__ outp) {
    int tid = threadIdx.x;
    if (tid < 24) {
        int b = tid / 3, c = tid % 3;
        float s = 0.f;
        for (int i = 0; i < 64; i++) s += g_gt[b][i][c] + g_eqsB[b][i][c];
        outp[OUT_XOUT + tid] = s * (1.f / (float)KTOP);
    }
}

/* ---------------- launch ---------------- */
extern "C" void kernel_launch(void* const* d_in, const int* in_sizes, int n_in,
                              void* d_out, int out_size) {
    const float* x   = (const float*)d_in[0];
    const float* w1  = (const float*)d_in[1];
    const float* b1  = (const float*)d_in[2];
    const float* w2  = (const float*)d_in[3];
    const float* b2  = (const float*)d_in[4];
    const float* cwm = (const float*)d_in[5];   /* color_w (3x3) */
    const float* cbm = (const float*)d_in[6];   /* color_b (3)   */
    const float* cw  = (const float*)d_in[7];   /* conv_w (4x3)  */
    const float* cb  = (const float*)d_in[8];   /* conv_b (4)    */
    float* out = (float*)d_out;

    cudaFuncSetAttribute(main_kernel, cudaFuncAttributeMaxDynamicSharedMemorySize, SMEM_BYTES);

    prep_kernel<<<1, 256>>>(w1, b1, w2, b2, cw, cb);
    meanA_kernel<<<dim3(8, 24), 256>>>(x);
    meanB_kernel<<<1, 32>>>(cwm, cbm);
    main_kernel<<<dim3(IMG_W/TW, IMG_H/TH, NB), 512, SMEM_BYTES>>>(x, out);
    brighthist_kernel<<<dim3(NPIX/2048, NB), 256>>>();
    scan_kernel<<<NB, 32>>>(0);
    for (int p = 1; p < 4; p++) {
        hist_kernel<<<dim3(256, NB), 256>>>(p);
        scan_kernel<<<NB, 32>>>(p);
    }
    sel1_kernel<<<dim3(64, NB), 256>>>(out);
    sel3_kernel<<<dim3(64, NB), 256>>>(out);
    sel4_kernel<<<1, 32>>>(out);
}

// round 14
// speedup vs baseline: 1.0612x; 1.0612x over previous
#include <cuda_runtime.h>
#include <math.h>

#define IMG_H 512
#define IMG_W 512
#define NB    8
#define NC    3
#define HID   64
#define NPIX  (IMG_H*IMG_W)
#define KTOP  26214
#define OUT_XOUT (NB*NC*NPIX)
#define PLANE NPIX
#define BSTRIDE (NC*NPIX)

#define TW 32
#define TH 16
#define HS_W 34           /* valid h cols */
#define HSTR 36           /* h row stride */
#define HROWS 18
#define HPLANE 652        /* 652 % 32 == 12 (4*odd) -> conflict-free lane-strided STS.128; mult of 4 -> aligned */

/* blob layout (floats) */
#define OFF_W1 0          /* [27 tap][64 oc]                     1728 */
#define OFF_W2 1728       /* [64 ic][9 tap][3 out x dup2]        3456 */
#define OFF_B1 5184       /* 64 */
#define OFF_B2 5248       /* 4  */
#define OFF_CW 5252       /* 12 */
#define OFF_CB 5264       /* 4  */
#define BLOB_FLOATS 5268
/* smem layout */
#define SM_COL 5268       /* 4 */
#define SM_X   5272       /* 3*20*36 = 2160 */
#define SM_H   7432       /* 64*652 = 41728 (conv2 partials alias this after sync) */
#define SMEM_FLOATS 49160
#define SMEM_BYTES (SMEM_FLOATS*4)

typedef unsigned long long ull;

__device__ float    g_blob[BLOB_FLOATS];
__device__ float    g_pmean[24*8];
__device__ float    g_color[24];
__device__ float    g_m[NB*NPIX];
__device__ float    g_bright[NB*NPIX];
__device__ unsigned g_hist[4][NB][256];
__device__ unsigned g_prefix[NB];
__device__ unsigned g_remk[NB];
__device__ float    g_gt[NB][64][3];
__device__ unsigned g_eqcB[NB][64];
__device__ float    g_eqsB[NB][64][3];

__device__ __forceinline__ ull pk2(float a, float b) {
    ull r; asm("mov.b64 %0,{%1,%2};" : "=l"(r) : "f"(a), "f"(b)); return r;
}
__device__ __forceinline__ ull pkd(float a) { return pk2(a, a); }
__device__ __forceinline__ void upk(ull v, float& lo, float& hi) {
    asm("mov.b64 {%0,%1},%2;" : "=f"(lo), "=f"(hi) : "l"(v));
}
__device__ __forceinline__ ull f2(ull a, ull b, ull c) {
    ull d; asm("fma.rn.f32x2 %0,%1,%2,%3;" : "=l"(d) : "l"(a), "l"(b), "l"(c)); return d;
}
__device__ __forceinline__ float sigm(float v) { return 1.f / (1.f + expf(-v)); }

/* ---------------- prep ---------------- */
__global__ void prep_kernel(const float* __restrict__ w1, const float* __restrict__ b1,
                            const float* __restrict__ w2, const float* __restrict__ b2,
                            const float* __restrict__ cw, const float* __restrict__ cb) {
    int tid = threadIdx.x;
    for (int i = tid; i < 1728; i += 256) {           /* w1: [oc][27] -> [tap][oc] */
        int t = i >> 6, oc = i & 63;
        g_blob[OFF_W1 + t*64 + oc] = w1[oc*27 + t];
    }
    for (int i = tid; i < 3456; i += 256) {           /* w2: [oc][ic][9] -> [ic][tap][o dup2] */
        int ic = i / 54, r = i % 54, t = r / 6, o = (r % 6) >> 1;
        g_blob[OFF_W2 + i] = w2[o*576 + ic*9 + t];
    }
    for (int i = tid; i < 64; i += 256) g_blob[OFF_B1 + i] = b1[i];
    if (tid < 4)  g_blob[OFF_B2 + tid] = (tid < 3) ? b2[tid] : 0.f;
    if (tid < 12) g_blob[OFF_CW + tid] = cw[tid];
    if (tid < 4)  g_blob[OFF_CB + tid] = cb[tid];
    unsigned* hz = &g_hist[0][0][0];
    for (int i = tid; i < 4*NB*256; i += 256) hz[i] = 0u;
    if (tid < NB) { g_prefix[tid] = 0u; g_remk[tid] = KTOP; }
}

/* ---------------- mean / color ---------------- */
__device__ float block_reduce256(float v, float* sbuf) {
    int tid = threadIdx.x;
    sbuf[tid] = v; __syncthreads();
    for (int s = 128; s > 0; s >>= 1) {
        if (tid < s) sbuf[tid] += sbuf[tid + s];
        __syncthreads();
    }
    float r = sbuf[0]; __syncthreads();
    return r;
}

__global__ void meanA_kernel(const float* __restrict__ x) {
    __shared__ float sbuf[256];
    int chunk = blockIdx.x, bc = blockIdx.y, tid = threadIdx.x;
    int base = bc * NPIX + chunk * 32768;
    float s = 0.f;
    for (int i = tid; i < 32768; i += 256) s += x[base + i];
    float r = block_reduce256(s, sbuf);
    if (tid == 0) g_pmean[bc*8 + chunk] = r;
}

__global__ void meanB_kernel(const float* __restrict__ color_w, const float* __restrict__ color_b) {
    __shared__ float mm[24];
    int tid = threadIdx.x;
    if (tid < 24) {
        float s = 0.f;
        for (int j = 0; j < 8; j++) s += g_pmean[tid*8 + j];
        mm[tid] = s * (1.f / (float)NPIX);
    }
    __syncthreads();
    if (tid < 24) {
        int b = tid / 3, c = tid % 3;
        float lin = color_b[c];
        for (int j = 0; j < 3; j++) lin += mm[b*3 + j] * color_w[c*3 + j];
        g_color[tid] = sigm(lin);
    }
}

/* ---------------- main fused kernel: 512 threads, 1 block/SM ---------------- */
__global__ void __launch_bounds__(512, 1)
main_kernel(const float* __restrict__ x, float* __restrict__ out) {
    extern __shared__ float sm[];
    int tid = threadIdx.x;
    int b  = blockIdx.z;
    int r0 = blockIdx.y * TH;
    int c0 = blockIdx.x * TW;

    for (int i = tid; i < BLOB_FLOATS; i += 512) sm[i] = g_blob[i];
    if (tid < 3) sm[SM_COL + tid] = g_color[b*3 + tid];

    /* x tile: 3 x 20 x 36, origin (r0-2, c0-2), zero outside image */
    for (int i = tid; i < 3*20*36; i += 512) {
        int ci = i / 720;
        int rr = (i % 720) / 36;
        int cc = i % 36;
        int gr = r0 - 2 + rr, gc = c0 - 2 + cc;
        float v = 0.f;
        if ((unsigned)gr < 512u && (unsigned)gc < 512u)
            v = x[b*BSTRIDE + ci*PLANE + gr*512 + gc];
        sm[SM_X + i] = v;
    }
    __syncthreads();

    /* ---- conv1: warp-per-quad, weights in registers ----
       lane owns oc pair (lane, lane+32) -> lane-stride HPLANE -> conflict-free STS.128.
       warp w handles quads w, w+16, ... (162 quads total). */
    {
        int warp = tid >> 5, lane = tid & 31;
        ull w[27];
        #pragma unroll
        for (int t = 0; t < 27; t++)
            w[t] = pk2(sm[OFF_W1 + t*64 + lane], sm[OFF_W1 + t*64 + lane + 32]);
        ull bias = pk2(sm[OFF_B1 + lane], sm[OFF_B1 + lane + 32]);

        for (int quad = warp; quad < 162; quad += 16) {
            int pr = quad / 9, pc0 = (quad % 9) << 2;
            ull acc0 = bias, acc1 = bias, acc2 = bias, acc3 = bias;
            #pragma unroll
            for (int ci = 0; ci < 3; ci++) {
                #pragma unroll
                for (int dr = 0; dr < 3; dr++) {
                    int xbase = SM_X + ci*720 + (pr+dr)*36 + pc0;
                    float4 xa = *(const float4*)&sm[xbase];
                    float2 xb = *(const float2*)&sm[xbase + 4];
                    ull x0 = pkd(xa.x), x1 = pkd(xa.y), x2 = pkd(xa.z);
                    ull x3 = pkd(xa.w), x4 = pkd(xb.x), x5 = pkd(xb.y);
                    const int tb = ci*9 + dr*3;
                    acc0 = f2(x0, w[tb+0], acc0); acc1 = f2(x1, w[tb+0], acc1);
                    acc2 = f2(x2, w[tb+0], acc2); acc3 = f2(x3, w[tb+0], acc3);
                    acc0 = f2(x1, w[tb+1], acc0); acc1 = f2(x2, w[tb+1], acc1);
                    acc2 = f2(x3, w[tb+1], acc2); acc3 = f2(x4, w[tb+1], acc3);
                    acc0 = f2(x2, w[tb+2], acc0); acc1 = f2(x3, w[tb+2], acc1);
                    acc2 = f2(x4, w[tb+2], acc2); acc3 = f2(x5, w[tb+2], acc3);
                }
            }
            int gr = r0 - 1 + pr;
            bool rok = ((unsigned)gr < 512u);
            float f[4][2];
            upk(acc0, f[0][0], f[0][1]); upk(acc1, f[1][0], f[1][1]);
            upk(acc2, f[2][0], f[2][1]); upk(acc3, f[3][0], f[3][1]);
            float4 v0, v1;
            float* pv0 = (float*)&v0;
            float* pv1 = (float*)&v1;
            #pragma unroll
            for (int j = 0; j < 4; j++) {
                int pc = pc0 + j;
                bool ok = rok && (pc < HS_W) && ((unsigned)(c0 - 1 + pc) < 512u);
                pv0[j] = ok ? fmaxf(f[j][0], 0.f) : 0.f;
                pv1[j] = ok ? fmaxf(f[j][1], 0.f) : 0.f;
            }
            *(float4*)&sm[SM_H + lane*HPLANE + pr*HSTR + pc0]      = v0;
            *(float4*)&sm[SM_H + (lane+32)*HPLANE + pr*HSTR + pc0] = v1;
        }
    }
    __syncthreads();

    /* ---- conv2: unit = 8 pixels (4 pairs) x 3 outs x 8 input channels ---- */
    ull a[4][3];
    int icg = tid >> 6;            /* 0..7 */
    int oct = tid & 63;            /* 0..63 */
    {
        int py  = oct >> 2;
        int px0 = (oct & 3) << 3;
        #pragma unroll
        for (int p = 0; p < 4; p++) { a[p][0] = 0ull; a[p][1] = 0ull; a[p][2] = 0ull; }

        int ic0 = icg * 8;
        for (int ic = ic0; ic < ic0 + 8; ic++) {
            const float* hb = &sm[SM_H + ic*HPLANE + py*HSTR + px0];
            const float* wb = &sm[OFF_W2 + ic*54];
            #pragma unroll
            for (int dr = 0; dr < 3; dr++) {
                float4 h0 = *(const float4*)&hb[dr*HSTR];
                float4 h1 = *(const float4*)&hb[dr*HSTR + 4];
                float2 h2 = *(const float2*)&hb[dr*HSTR + 8];
                ull p01 = pk2(h0.x, h0.y), p23 = pk2(h0.z, h0.w);
                ull p45 = pk2(h1.x, h1.y), p67 = pk2(h1.z, h1.w);
                ull p89 = pk2(h2.x, h2.y);
                ull p12 = pk2(h0.y, h0.z), p34 = pk2(h0.w, h1.x);
                ull p56 = pk2(h1.y, h1.z), p78 = pk2(h1.w, h2.x);
                const ull* wp0 = (const ull*)&wb[(dr*3 + 0)*6];
                const ull* wp1 = (const ull*)&wb[(dr*3 + 1)*6];
                const ull* wp2 = (const ull*)&wb[(dr*3 + 2)*6];
                {
                    ull w0 = wp0[0], w1 = wp0[1], w2 = wp0[2];
                    a[0][0]=f2(p01,w0,a[0][0]); a[0][1]=f2(p01,w1,a[0][1]); a[0][2]=f2(p01,w2,a[0][2]);
                    a[1][0]=f2(p23,w0,a[1][0]); a[1][1]=f2(p23,w1,a[1][1]); a[1][2]=f2(p23,w2,a[1][2]);
                    a[2][0]=f2(p45,w0,a[2][0]); a[2][1]=f2(p45,w1,a[2][1]); a[2][2]=f2(p45,w2,a[2][2]);
                    a[3][0]=f2(p67,w0,a[3][0]); a[3][1]=f2(p67,w1,a[3][1]); a[3][2]=f2(p67,w2,a[3][2]);
                }
                {
                    ull w0 = wp1[0], w1 = wp1[1], w2 = wp1[2];
                    a[0][0]=f2(p12,w0,a[0][0]); a[0][1]=f2(p12,w1,a[0][1]); a[0][2]=f2(p12,w2,a[0][2]);
                    a[1][0]=f2(p34,w0,a[1][0]); a[1][1]=f2(p34,w1,a[1][1]); a[1][2]=f2(p34,w2,a[1][2]);
                    a[2][0]=f2(p56,w0,a[2][0]); a[2][1]=f2(p56,w1,a[2][1]); a[2][2]=f2(p56,w2,a[2][2]);
                    a[3][0]=f2(p78,w0,a[3][0]); a[3][1]=f2(p78,w1,a[3][1]); a[3][2]=f2(p78,w2,a[3][2]);
                }
                {
                    ull w0 = wp2[0], w1 = wp2[1], w2 = wp2[2];
                    a[0][0]=f2(p23,w0,a[0][0]); a[0][1]=f2(p23,w1,a[0][1]); a[0][2]=f2(p23,w2,a[0][2]);
                    a[1][0]=f2(p45,w0,a[1][0]); a[1][1]=f2(p45,w1,a[1][1]); a[1][2]=f2(p45,w2,a[1][2]);
                    a[2][0]=f2(p67,w0,a[2][0]); a[2][1]=f2(p67,w1,a[2][1]); a[2][2]=f2(p67,w2,a[2][2]);
                    a[3][0]=f2(p89,w0,a[3][0]); a[3][1]=f2(p89,w1,a[3][1]); a[3][2]=f2(p89,w2,a[3][2]);
                }
            }
        }
    }
    __syncthreads();   /* all H reads done; RED aliases H region */
    {
        float* rp = &sm[SM_H + (oct*8 + icg)*24];
        #pragma unroll
        for (int o = 0; o < 3; o++) {
            #pragma unroll
            for (int p = 0; p < 4; p++) {
                float lo, hi; upk(a[p][o], lo, hi);
                rp[o*8 + 2*p]     = lo;
                rp[o*8 + 2*p + 1] = hi;
            }
        }
    }
    __syncthreads();

    /* ---- finalize: sum partials, sigmoid + color + 1x1 + x_out ---- */
    {
        int py = tid >> 5, px = tid & 31;
        int o8 = py*4 + (px >> 3), jj = px & 7;
        float s0 = sm[OFF_B2], s1 = sm[OFF_B2+1], s2 = sm[OFF_B2+2];
        #pragma unroll
        for (int g = 0; g < 8; g++) {
            const float* rp = &sm[SM_H + (o8*8 + g)*24];
            s0 += rp[jj]; s1 += rp[8 + jj]; s2 += rp[16 + jj];
        }
        float ih0 = sigm(s0) * sm[SM_COL + 0];
        float ih1 = sigm(s1) * sm[SM_COL + 1];
        float ih2 = sigm(s2) * sm[SM_COL + 2];
        const float* cw = &sm[OFF_CW];
        const float* cb = &sm[OFF_CB];
        float K = cb[0] + cw[0]*ih0 + cw[1]*ih1 + cw[2]*ih2;
        int pix = (r0 + py)*512 + (c0 + px);
        float mx = -1e30f;
        #pragma unroll
        for (int c = 0; c < 3; c++) {
            float Bt = cb[1+c] + cw[(1+c)*3+0]*ih0 + cw[(1+c)*3+1]*ih1 + cw[(1+c)*3+2]*ih2;
            float xv = sm[SM_X + c*720 + (py+2)*36 + (px+2)];
            float xo = K*xv - Bt + xv;
            out[b*BSTRIDE + c*PLANE + pix] = xo;
            mx = fmaxf(mx, xo);
        }
        g_m[b*NPIX + pix] = mx;
    }
}

/* ---------------- bright (reflect pad, 3x3) + fused radix pass-0 hist ---------------- */
__global__ void brighthist_kernel() {
    __shared__ unsigned h[256];
    int b = blockIdx.y, tid = threadIdx.x;
    h[tid] = 0; __syncthreads();
    const float* m = &g_m[b*NPIX];
    int base = blockIdx.x*2048;
    #pragma unroll
    for (int k = 0; k < 8; k++) {
        int p = base + k*256 + tid;
        int r = p >> 9, c = p & 511;
        float acc = 0.f;
        #pragma unroll
        for (int dr = 0; dr < 3; dr++) {
            int rr = r + dr - 1; rr = rr < 0 ? 1 : (rr > 511 ? 510 : rr);
            #pragma unroll
            for (int dc = 0; dc < 3; dc++) {
                int cc = c + dc - 1; cc = cc < 0 ? 1 : (cc > 511 ? 510 : cc);
                float w = (dr == 1 && dc == 1) ? 1.0f : (1.f/9.f);
                acc += w * m[rr*512 + cc];
            }
        }
        float bv = fmaxf(acc, 0.f);
        g_bright[b*NPIX + p] = bv;
        atomicAdd(&h[__float_as_uint(bv) >> 24], 1u);
    }
    __syncthreads();
    if (h[tid]) atomicAdd(&g_hist[0][b][tid], h[tid]);
}

/* ---------------- radix select (passes 1-3) ---------------- */
__global__ void hist_kernel(int pass) {
    __shared__ unsigned h[256];
    int b = blockIdx.y, tid = threadIdx.x;
    h[tid] = 0; __syncthreads();
    unsigned pref = g_prefix[b];
    int shift = 24 - 8*pass;
    int base = b*NPIX + blockIdx.x*1024;
    for (int i = tid; i < 1024; i += 256) {
        unsigned u = __float_as_uint(g_bright[base + i]);
        if ((u >> (shift + 8)) == pref) atomicAdd(&h[(u >> shift) & 255], 1u);
    }
    __syncthreads();
    if (h[tid]) atomicAdd(&g_hist[pass][b][tid], h[tid]);
}

__global__ void scan_kernel(int pass) {
    int b = blockIdx.x;
    if (threadIdx.x == 0) {
        unsigned remk = g_remk[b], cum = 0, pref = g_prefix[b], sel = 0;
        for (int bin = 255; bin >= 0; bin--) {
            unsigned c = g_hist[pass][b][bin];
            if (cum + c >= remk) { sel = (unsigned)bin; break; }
            cum += c;
        }
        g_prefix[b] = (pref << 8) | sel;
        g_remk[b] = remk - cum;
    }
}

__global__ void sel1_kernel(const float* __restrict__ outp) {
    __shared__ float s0[256], s1[256], s2[256];
    __shared__ unsigned sc[256];
    int b = blockIdx.y, blk = blockIdx.x, tid = threadIdx.x;
    unsigned T = g_prefix[b];
    const float* br  = &g_bright[b*NPIX];
    const float* img = outp + b*BSTRIDE;
    int base = blk*4096;
    float a0 = 0, a1 = 0, a2 = 0; unsigned ec = 0;
    for (int i = tid; i < 4096; i += 256) {
        int p = base + i;
        unsigned u = __float_as_uint(br[p]);
        if (u > T) { a0 += img[p*3]; a1 += img[p*3+1]; a2 += img[p*3+2]; }
        else if (u == T) ec++;
    }
    s0[tid]=a0; s1[tid]=a1; s2[tid]=a2; sc[tid]=ec; __syncthreads();
    for (int s = 128; s > 0; s >>= 1) {
        if (tid < s) { s0[tid]+=s0[tid+s]; s1[tid]+=s1[tid+s]; s2[tid]+=s2[tid+s]; sc[tid]+=sc[tid+s]; }
        __syncthreads();
    }
    if (tid == 0) {
        g_gt[b][blk][0]=s0[0]; g_gt[b][blk][1]=s1[0]; g_gt[b][blk][2]=s2[0];
        g_eqcB[b][blk]=sc[0];
    }
}

__global__ void sel3_kernel(const float* __restrict__ outp) {
    __shared__ unsigned scnt[256];
    __shared__ unsigned eqc[64];
    __shared__ unsigned startsh;
    __shared__ float s0[256], s1[256], s2[256];
    int b = blockIdx.y, blk = blockIdx.x, tid = threadIdx.x;
    unsigned T = g_prefix[b], remk = g_remk[b];
    const float* br  = &g_bright[b*NPIX];
    const float* img = outp + b*BSTRIDE;
    if (tid < 64) eqc[tid] = g_eqcB[b][tid];
    int start = blk*4096 + tid*16;
    unsigned cnt = 0;
    for (int j = 0; j < 16; j++) if (__float_as_uint(br[start+j]) == T) cnt++;
    scnt[tid] = cnt; __syncthreads();
    if (tid == 0) {
        unsigned run = 0;
        for (int i = 0; i < blk; i++) run += eqc[i];
        startsh = run;
        run = 0;
        for (int i = 0; i < 256; i++) { unsigned c = scnt[i]; scnt[i] = run; run += c; }
    }
    __syncthreads();
    unsigned rank = startsh + scnt[tid];
    float a0 = 0, a1 = 0, a2 = 0;
    for (int j = 0; j < 16; j++) {
        int p = start + j;
        if (__float_as_uint(br[p]) == T) {
            if (rank < remk) { a0 += img[p*3]; a1 += img[p*3+1]; a2 += img[p*3+2]; }
            rank++;
        }
    }
    s0[tid]=a0; s1[tid]=a1; s2[tid]=a2; __syncthreads();
    for (int s = 128; s > 0; s >>= 1) {
        if (tid < s) { s0[tid]+=s0[tid+s]; s1[tid]+=s1[tid+s]; s2[tid]+=s2[tid+s]; }
        __syncthreads();
    }
    if (tid == 0) { g_eqsB[b][blk][0]=s0[0]; g_eqsB[b][blk][1]=s1[0]; g_eqsB[b][blk][2]=s2[0]; }
}

__global__ void sel4_kernel(float* __restrict__ outp) {
    int tid = threadIdx.x;
    if (tid < 24) {
        int b = tid / 3, c = tid % 3;
        float s = 0.f;
        for (int i = 0; i < 64; i++) s += g_gt[b][i][c] + g_eqsB[b][i][c];
        outp[OUT_XOUT + tid] = s * (1.f / (float)KTOP);
    }
}

/* ---------------- launch ---------------- */
extern "C" void kernel_launch(void* const* d_in, const int* in_sizes, int n_in,
                              void* d_out, int out_size) {
    const float* x   = (const float*)d_in[0];
    const float* w1  = (const float*)d_in[1];
    const float* b1  = (const float*)d_in[2];
    const float* w2  = (const float*)d_in[3];
    const float* b2  = (const float*)d_in[4];
    const float* cwm = (const float*)d_in[5];   /* color_w (3x3) */
    const float* cbm = (const float*)d_in[6];   /* color_b (3)   */
    const float* cw  = (const float*)d_in[7];   /* conv_w (4x3)  */
    const float* cb  = (const float*)d_in[8];   /* conv_b (4)    */
    float* out = (float*)d_out;

    cudaFuncSetAttribute(main_kernel, cudaFuncAttributeMaxDynamicSharedMemorySize, SMEM_BYTES);

    prep_kernel<<<1, 256>>>(w1, b1, w2, b2, cw, cb);
    meanA_kernel<<<dim3(8, 24), 256>>>(x);
    meanB_kernel<<<1, 32>>>(cwm, cbm);
    main_kernel<<<dim3(IMG_W/TW, IMG_H/TH, NB), 512, SMEM_BYTES>>>(x, out);
    brighthist_kernel<<<dim3(NPIX/2048, NB), 256>>>();
    scan_kernel<<<NB, 32>>>(0);
    for (int p = 1; p < 4; p++) {
        hist_kernel<<<dim3(256, NB), 256>>>(p);
        scan_kernel<<<NB, 32>>>(p);
    }
    sel1_kernel<<<dim3(64, NB), 256>>>(out);
    sel3_kernel<<<dim3(64, NB), 256>>>(out);
    sel4_kernel<<<1, 32>>>(out);
}

// round 15
// speedup vs baseline: 1.1149x; 1.0507x over previous
#include <cuda_runtime.h>
#include <math.h>

#define IMG_H 512
#define IMG_W 512
#define NB    8
#define NC    3
#define HID   64
#define NPIX  (IMG_H*IMG_W)
#define KTOP  26214
#define OUT_XOUT (NB*NC*NPIX)
#define PLANE NPIX
#define BSTRIDE (NC*NPIX)

#define TW 32
#define TH 16
#define HS_W 34
#define HROWS 18
#define PP2 1300          /* floats per icPair plane (648 pairs = 1296, pad to 1300: %4==0, %32==4) */

/* blob layout (floats) */
#define OFF_W1 0          /* [27 tap][64 oc]                          1728 */
#define OFF_W2 1728       /* [32 icPair][9 tap][3 o][2 ic-halves]     1728 */
#define OFF_B1 3456       /* 64 */
#define OFF_B2 3520       /* 4  */
#define OFF_CW 3524       /* 12 */
#define OFF_CB 3536       /* 4  */
#define BLOB_FLOATS 3540
/* smem layout */
#define SM_COL 3540       /* 4 */
#define SM_X   3544       /* 3*20*36 = 2160 */
#define SM_H   5704       /* 32*1300 = 41600 (conv2 partials alias after sync) */
#define SMEM_FLOATS 47304
#define SMEM_BYTES (SMEM_FLOATS*4)

typedef unsigned long long ull;

__device__ float    g_blob[BLOB_FLOATS];
__device__ float    g_pmean[24*8];
__device__ float    g_color[24];
__device__ float    g_m[NB*NPIX];
__device__ float    g_bright[NB*NPIX];
__device__ unsigned g_hist[4][NB][256];
__device__ unsigned g_prefix[NB];
__device__ unsigned g_remk[NB];
__device__ float    g_gt[NB][64][3];
__device__ unsigned g_eqcB[NB][64];
__device__ float    g_eqsB[NB][64][3];

__device__ __forceinline__ ull pk2(float a, float b) {
    ull r; asm("mov.b64 %0,{%1,%2};" : "=l"(r) : "f"(a), "f"(b)); return r;
}
__device__ __forceinline__ ull pkd(float a) { return pk2(a, a); }
__device__ __forceinline__ void upk(ull v, float& lo, float& hi) {
    asm("mov.b64 {%0,%1},%2;" : "=f"(lo), "=f"(hi) : "l"(v));
}
__device__ __forceinline__ ull f2(ull a, ull b, ull c) {
    ull d; asm("fma.rn.f32x2 %0,%1,%2,%3;" : "=l"(d) : "l"(a), "l"(b), "l"(c)); return d;
}
__device__ __forceinline__ float sigm(float v) { return 1.f / (1.f + expf(-v)); }

/* ---------------- prep ---------------- */
__global__ void prep_kernel(const float* __restrict__ w1, const float* __restrict__ b1,
                            const float* __restrict__ w2, const float* __restrict__ b2,
                            const float* __restrict__ cw, const float* __restrict__ cb) {
    int tid = threadIdx.x;
    for (int i = tid; i < 1728; i += 256) {           /* w1: [oc][27] -> [tap][oc] */
        int t = i >> 6, oc = i & 63;
        g_blob[OFF_W1 + t*64 + oc] = w1[oc*27 + t];
    }
    for (int i = tid; i < 1728; i += 256) {           /* w2: [o][ic][9] -> [icPair][tap][o][2] */
        int ip = i / 54, r = i % 54, t = r / 6, o = (r % 6) >> 1, k = r & 1;
        g_blob[OFF_W2 + i] = w2[o*576 + (2*ip + k)*9 + t];
    }
    for (int i = tid; i < 64; i += 256) g_blob[OFF_B1 + i] = b1[i];
    if (tid < 4)  g_blob[OFF_B2 + tid] = (tid < 3) ? b2[tid] : 0.f;
    if (tid < 12) g_blob[OFF_CW + tid] = cw[tid];
    if (tid < 4)  g_blob[OFF_CB + tid] = cb[tid];
    unsigned* hz = &g_hist[0][0][0];
    for (int i = tid; i < 4*NB*256; i += 256) hz[i] = 0u;
    if (tid < NB) { g_prefix[tid] = 0u; g_remk[tid] = KTOP; }
}

/* ---------------- mean / color ---------------- */
__device__ float block_reduce256(float v, float* sbuf) {
    int tid = threadIdx.x;
    sbuf[tid] = v; __syncthreads();
    for (int s = 128; s > 0; s >>= 1) {
        if (tid < s) sbuf[tid] += sbuf[tid + s];
        __syncthreads();
    }
    float r = sbuf[0]; __syncthreads();
    return r;
}

__global__ void meanA_kernel(const float* __restrict__ x) {
    __shared__ float sbuf[256];
    int chunk = blockIdx.x, bc = blockIdx.y, tid = threadIdx.x;
    int base = bc * NPIX + chunk * 32768;
    float s = 0.f;
    for (int i = tid; i < 32768; i += 256) s += x[base + i];
    float r = block_reduce256(s, sbuf);
    if (tid == 0) g_pmean[bc*8 + chunk] = r;
}

__global__ void meanB_kernel(const float* __restrict__ color_w, const float* __restrict__ color_b) {
    __shared__ float mm[24];
    int tid = threadIdx.x;
    if (tid < 24) {
        float s = 0.f;
        for (int j = 0; j < 8; j++) s += g_pmean[tid*8 + j];
        mm[tid] = s * (1.f / (float)NPIX);
    }
    __syncthreads();
    if (tid < 24) {
        int b = tid / 3, c = tid % 3;
        float lin = color_b[c];
        for (int j = 0; j < 3; j++) lin += mm[b*3 + j] * color_w[c*3 + j];
        g_color[tid] = sigm(lin);
    }
}

/* ---------------- main fused kernel: 512 threads, 1 block/SM ---------------- */
__global__ void __launch_bounds__(512, 1)
main_kernel(const float* __restrict__ x, float* __restrict__ out) {
    extern __shared__ float sm[];
    int tid = threadIdx.x;
    int b  = blockIdx.z;
    int r0 = blockIdx.y * TH;
    int c0 = blockIdx.x * TW;

    for (int i = tid; i < BLOB_FLOATS; i += 512) sm[i] = g_blob[i];
    if (tid < 3) sm[SM_COL + tid] = g_color[b*3 + tid];

    /* x tile: 3 x 20 x 36, origin (r0-2, c0-2), zero outside image */
    for (int i = tid; i < 3*20*36; i += 512) {
        int ci = i / 720;
        int rr = (i % 720) / 36;
        int cc = i % 36;
        int gr = r0 - 2 + rr, gc = c0 - 2 + cc;
        float v = 0.f;
        if ((unsigned)gr < 512u && (unsigned)gc < 512u)
            v = x[b*BSTRIDE + ci*PLANE + gr*512 + gc];
        sm[SM_X + i] = v;
    }
    __syncthreads();

    /* ---- conv1: warp-per-quad; lane owns oc pair (2*lane, 2*lane+1) ----
       acc u64 IS the channel pair -> stored directly as STS.64, pair-interleaved. */
    {
        int warp = tid >> 5, lane = tid & 31;
        ull w[27];
        #pragma unroll
        for (int t = 0; t < 27; t++)
            w[t] = *(const ull*)&sm[OFF_W1 + t*64 + 2*lane];
        ull bias = *(const ull*)&sm[OFF_B1 + 2*lane];

        for (int quad = warp; quad < 162; quad += 16) {
            int pr = quad / 9, pc0 = (quad % 9) << 2;
            ull acc0 = bias, acc1 = bias, acc2 = bias, acc3 = bias;
            #pragma unroll
            for (int ci = 0; ci < 3; ci++) {
                #pragma unroll
                for (int dr = 0; dr < 3; dr++) {
                    int xbase = SM_X + ci*720 + (pr+dr)*36 + pc0;
                    float4 xa = *(const float4*)&sm[xbase];
                    float2 xb = *(const float2*)&sm[xbase + 4];
                    ull x0 = pkd(xa.x), x1 = pkd(xa.y), x2 = pkd(xa.z);
                    ull x3 = pkd(xa.w), x4 = pkd(xb.x), x5 = pkd(xb.y);
                    const int tb = ci*9 + dr*3;
                    acc0 = f2(x0, w[tb+0], acc0); acc1 = f2(x1, w[tb+0], acc1);
                    acc2 = f2(x2, w[tb+0], acc2); acc3 = f2(x3, w[tb+0], acc3);
                    acc0 = f2(x1, w[tb+1], acc0); acc1 = f2(x2, w[tb+1], acc1);
                    acc2 = f2(x3, w[tb+1], acc2); acc3 = f2(x4, w[tb+1], acc3);
                    acc0 = f2(x2, w[tb+2], acc0); acc1 = f2(x3, w[tb+2], acc1);
                    acc2 = f2(x4, w[tb+2], acc2); acc3 = f2(x5, w[tb+2], acc3);
                }
            }
            int gr = r0 - 1 + pr;
            bool rok = ((unsigned)gr < 512u);
            ull av[4]; av[0]=acc0; av[1]=acc1; av[2]=acc2; av[3]=acc3;
            #pragma unroll
            for (int j = 0; j < 4; j++) {
                int pc = pc0 + j;
                bool ok = rok && (pc < HS_W) && ((unsigned)(c0 - 1 + pc) < 512u);
                float lo, hi; upk(av[j], lo, hi);
                ull pair = ok ? pk2(fmaxf(lo, 0.f), fmaxf(hi, 0.f)) : 0ull;
                *(ull*)&sm[SM_H + lane*PP2 + (pr*36 + pc)*2] = pair;
            }
        }
    }
    __syncthreads();

    /* ---- conv2: unit = 4 pixels x 3 outs x 8 icPairs; pair dim = input channels ----
       128 pixel-quads x 4 groups = 512 threads; zero packs. */
    ull a[4][3];
    int grp = tid >> 7;            /* 0..3 : icPair group */
    int q   = tid & 127;           /* pixel quad */
    {
        int py  = q >> 3;          /* 0..15 */
        int px0 = (q & 7) << 2;    /* 0..28 */
        #pragma unroll
        for (int p = 0; p < 4; p++) { a[p][0] = 0ull; a[p][1] = 0ull; a[p][2] = 0ull; }

        int ip0 = grp * 8;
        for (int ip = ip0; ip < ip0 + 8; ip++) {
            const float* hb = &sm[SM_H + ip*PP2];
            const float* wb = &sm[OFF_W2 + ip*54];
            #pragma unroll
            for (int dr = 0; dr < 3; dr++) {
                const ull* hp = (const ull*)&hb[((py+dr)*36 + px0)*2];
                ull h0 = hp[0], h1 = hp[1], h2 = hp[2], h3 = hp[3], h4 = hp[4], h5 = hp[5];
                const ull* wrow = (const ull*)&wb[dr*18];
                {   /* dc = 0 */
                    ull w0 = wrow[0], w1 = wrow[1], w2 = wrow[2];
                    a[0][0]=f2(h0,w0,a[0][0]); a[0][1]=f2(h0,w1,a[0][1]); a[0][2]=f2(h0,w2,a[0][2]);
                    a[1][0]=f2(h1,w0,a[1][0]); a[1][1]=f2(h1,w1,a[1][1]); a[1][2]=f2(h1,w2,a[1][2]);
                    a[2][0]=f2(h2,w0,a[2][0]); a[2][1]=f2(h2,w1,a[2][1]); a[2][2]=f2(h2,w2,a[2][2]);
                    a[3][0]=f2(h3,w0,a[3][0]); a[3][1]=f2(h3,w1,a[3][1]); a[3][2]=f2(h3,w2,a[3][2]);
                }
                {   /* dc = 1 */
                    ull w0 = wrow[3], w1 = wrow[4], w2 = wrow[5];
                    a[0][0]=f2(h1,w0,a[0][0]); a[0][1]=f2(h1,w1,a[0][1]); a[0][2]=f2(h1,w2,a[0][2]);
                    a[1][0]=f2(h2,w0,a[1][0]); a[1][1]=f2(h2,w1,a[1][1]); a[1][2]=f2(h2,w2,a[1][2]);
                    a[2][0]=f2(h3,w0,a[2][0]); a[2][1]=f2(h3,w1,a[2][1]); a[2][2]=f2(h3,w2,a[2][2]);
                    a[3][0]=f2(h4,w0,a[3][0]); a[3][1]=f2(h4,w1,a[3][1]); a[3][2]=f2(h4,w2,a[3][2]);
                }
                {   /* dc = 2 */
                    ull w0 = wrow[6], w1 = wrow[7], w2 = wrow[8];
                    a[0][0]=f2(h2,w0,a[0][0]); a[0][1]=f2(h2,w1,a[0][1]); a[0][2]=f2(h2,w2,a[0][2]);
                    a[1][0]=f2(h3,w0,a[1][0]); a[1][1]=f2(h3,w1,a[1][1]); a[1][2]=f2(h3,w2,a[1][2]);
                    a[2][0]=f2(h4,w0,a[2][0]); a[2][1]=f2(h4,w1,a[2][1]); a[2][2]=f2(h4,w2,a[2][2]);
                    a[3][0]=f2(h5,w0,a[3][0]); a[3][1]=f2(h5,w1,a[3][1]); a[3][2]=f2(h5,w2,a[3][2]);
                }
            }
        }
    }
    __syncthreads();   /* all H reads done; RED aliases H region */
    {
        /* fold (lo+hi) = sum over the ic pair; write 12 scalars */
        float* rp = &sm[SM_H + (q*4 + grp)*12];
        #pragma unroll
        for (int o = 0; o < 3; o++) {
            #pragma unroll
            for (int p = 0; p < 4; p++) {
                float lo, hi; upk(a[p][o], lo, hi);
                rp[o*4 + p] = lo + hi;
            }
        }
    }
    __syncthreads();

    /* ---- finalize: sum partials, sigmoid + color + 1x1 + x_out ---- */
    {
        int py = tid >> 5, px = tid & 31;
        int q2 = py*8 + (px >> 2), j = px & 3;
        float s0 = sm[OFF_B2], s1 = sm[OFF_B2+1], s2 = sm[OFF_B2+2];
        #pragma unroll
        for (int g = 0; g < 4; g++) {
            const float* rp = &sm[SM_H + (q2*4 + g)*12];
            s0 += rp[j]; s1 += rp[4 + j]; s2 += rp[8 + j];
        }
        float ih0 = sigm(s0) * sm[SM_COL + 0];
        float ih1 = sigm(s1) * sm[SM_COL + 1];
        float ih2 = sigm(s2) * sm[SM_COL + 2];
        const float* cw = &sm[OFF_CW];
        const float* cb = &sm[OFF_CB];
        float K = cb[0] + cw[0]*ih0 + cw[1]*ih1 + cw[2]*ih2;
        int pix = (r0 + py)*512 + (c0 + px);
        float mx = -1e30f;
        #pragma unroll
        for (int c = 0; c < 3; c++) {
            float Bt = cb[1+c] + cw[(1+c)*3+0]*ih0 + cw[(1+c)*3+1]*ih1 + cw[(1+c)*3+2]*ih2;
            float xv = sm[SM_X + c*720 + (py+2)*36 + (px+2)];
            float xo = K*xv - Bt + xv;
            out[b*BSTRIDE + c*PLANE + pix] = xo;
            mx = fmaxf(mx, xo);
        }
        g_m[b*NPIX + pix] = mx;
    }
}

/* ---------------- bright (reflect pad, 3x3) + fused radix pass-0 hist ---------------- */
__global__ void brighthist_kernel() {
    __shared__ unsigned h[256];
    int b = blockIdx.y, tid = threadIdx.x;
    h[tid] = 0; __syncthreads();
    const float* m = &g_m[b*NPIX];
    int base = blockIdx.x*2048;
    #pragma unroll
    for (int k = 0; k < 8; k++) {
        int p = base + k*256 + tid;
        int r = p >> 9, c = p & 511;
        float acc = 0.f;
        #pragma unroll
        for (int dr = 0; dr < 3; dr++) {
            int rr = r + dr - 1; rr = rr < 0 ? 1 : (rr > 511 ? 510 : rr);
            #pragma unroll
            for (int dc = 0; dc < 3; dc++) {
                int cc = c + dc - 1; cc = cc < 0 ? 1 : (cc > 511 ? 510 : cc);
                float w = (dr == 1 && dc == 1) ? 1.0f : (1.f/9.f);
                acc += w * m[rr*512 + cc];
            }
        }
        float bv = fmaxf(acc, 0.f);
        g_bright[b*NPIX + p] = bv;
        atomicAdd(&h[__float_as_uint(bv) >> 24], 1u);
    }
    __syncthreads();
    if (h[tid]) atomicAdd(&g_hist[0][b][tid], h[tid]);
}

/* ---------------- radix select (passes 1-3) ---------------- */
__global__ void hist_kernel(int pass) {
    __shared__ unsigned h[256];
    int b = blockIdx.y, tid = threadIdx.x;
    h[tid] = 0; __syncthreads();
    unsigned pref = g_prefix[b];
    int shift = 24 - 8*pass;
    int base = b*NPIX + blockIdx.x*1024;
    for (int i = tid; i < 1024; i += 256) {
        unsigned u = __float_as_uint(g_bright[base + i]);
        if ((u >> (shift + 8)) == pref) atomicAdd(&h[(u >> shift) & 255], 1u);
    }
    __syncthreads();
    if (h[tid]) atomicAdd(&g_hist[pass][b][tid], h[tid]);
}

__global__ void scan_kernel(int pass) {
    int b = blockIdx.x;
    if (threadIdx.x == 0) {
        unsigned remk = g_remk[b], cum = 0, pref = g_prefix[b], sel = 0;
        for (int bin = 255; bin >= 0; bin--) {
            unsigned c = g_hist[pass][b][bin];
            if (cum + c >= remk) { sel = (unsigned)bin; break; }
            cum += c;
        }
        g_prefix[b] = (pref << 8) | sel;
        g_remk[b] = remk - cum;
    }
}

__global__ void sel1_kernel(const float* __restrict__ outp) {
    __shared__ float s0[256], s1[256], s2[256];
    __shared__ unsigned sc[256];
    int b = blockIdx.y, blk = blockIdx.x, tid = threadIdx.x;
    unsigned T = g_prefix[b];
    const float* br  = &g_bright[b*NPIX];
    const float* img = outp + b*BSTRIDE;
    int base = blk*4096;
    float a0 = 0, a1 = 0, a2 = 0; unsigned ec = 0;
    for (int i = tid; i < 4096; i += 256) {
        int p = base + i;
        unsigned u = __float_as_uint(br[p]);
        if (u > T) { a0 += img[p*3]; a1 += img[p*3+1]; a2 += img[p*3+2]; }
        else if (u == T) ec++;
    }
    s0[tid]=a0; s1[tid]=a1; s2[tid]=a2; sc[tid]=ec; __syncthreads();
    for (int s = 128; s > 0; s >>= 1) {
        if (tid < s) { s0[tid]+=s0[tid+s]; s1[tid]+=s1[tid+s]; s2[tid]+=s2[tid+s]; sc[tid]+=sc[tid+s]; }
        __syncthreads();
    }
    if (tid == 0) {
        g_gt[b][blk][0]=s0[0]; g_gt[b][blk][1]=s1[0]; g_gt[b][blk][2]=s2[0];
        g_eqcB[b][blk]=sc[0];
    }
}

__global__ void sel3_kernel(const float* __restrict__ outp) {
    __shared__ unsigned scnt[256];
    __shared__ unsigned eqc[64];
    __shared__ unsigned startsh;
    __shared__ float s0[256], s1[256], s2[256];
    int b = blockIdx.y, blk = blockIdx.x, tid = threadIdx.x;
    unsigned T = g_prefix[b], remk = g_remk[b];
    const float* br  = &g_bright[b*NPIX];
    const float* img = outp + b*BSTRIDE;
    if (tid < 64) eqc[tid] = g_eqcB[b][tid];
    int start = blk*4096 + tid*16;
    unsigned cnt = 0;
    for (int j = 0; j < 16; j++) if (__float_as_uint(br[start+j]) == T) cnt++;
    scnt[tid] = cnt; __syncthreads();
    if (tid == 0) {
        unsigned run = 0;
        for (int i = 0; i < blk; i++) run += eqc[i];
        startsh = run;
        run = 0;
        for (int i = 0; i < 256; i++) { unsigned c = scnt[i]; scnt[i] = run; run += c; }
    }
    __syncthreads();
    unsigned rank = startsh + scnt[tid];
    float a0 = 0, a1 = 0, a2 = 0;
    for (int j = 0; j < 16; j++) {
        int p = start + j;
        if (__float_as_uint(br[p]) == T) {
            if (rank < remk) { a0 += img[p*3]; a1 += img[p*3+1]; a2 += img[p*3+2]; }
            rank++;
        }
    }
    s0[tid]=a0; s1[tid]=a1; s2[tid]=a2; __syncthreads();
    for (int s = 128; s > 0; s >>= 1) {
        if (tid < s) { s0[tid]+=s0[tid+s]; s1[tid]+=s1[tid+s]; s2[tid]+=s2[tid+s]; }
        __syncthreads();
    }
    if (tid == 0) { g_eqsB[b][blk][0]=s0[0]; g_eqsB[b][blk][1]=s1[0]; g_eqsB[b][blk][2]=s2[0]; }
}

__global__ void sel4_kernel(float* __restrict__ outp) {
    int tid = threadIdx.x;
    if (tid < 24) {
        int b = tid / 3, c = tid % 3;
        float s = 0.f;
        for (int i = 0; i < 64; i++) s += g_gt[b][i][c] + g_eqsB[b][i][c];
        outp[OUT_XOUT + tid] = s * (1.f / (float)KTOP);
    }
}

/* ---------------- launch ---------------- */
extern "C" void kernel_launch(void* const* d_in, const int* in_sizes, int n_in,
                              void* d_out, int out_size) {
    const float* x   = (const float*)d_in[0];
    const float* w1  = (const float*)d_in[1];
    const float* b1  = (const float*)d_in[2];
    const float* w2  = (const float*)d_in[3];
    const float* b2  = (const float*)d_in[4];
    const float* cwm = (const float*)d_in[5];   /* color_w (3x3) */
    const float* cbm = (const float*)d_in[6];   /* color_b (3)   */
    const float* cw  = (const float*)d_in[7];   /* conv_w (4x3)  */
    const float* cb  = (const float*)d_in[8];   /* conv_b (4)    */
    float* out = (float*)d_out;

    cudaFuncSetAttribute(main_kernel, cudaFuncAttributeMaxDynamicSharedMemorySize, SMEM_BYTES);

    prep_kernel<<<1, 256>>>(w1, b1, w2, b2, cw, cb);
    meanA_kernel<<<dim3(8, 24), 256>>>(x);
    meanB_kernel<<<1, 32>>>(cwm, cbm);
    main_kernel<<<dim3(IMG_W/TW, IMG_H/TH, NB), 512, SMEM_BYTES>>>(x, out);
    brighthist_kernel<<<dim3(NPIX/2048, NB), 256>>>();
    scan_kernel<<<NB, 32>>>(0);
    for (int p = 1; p < 4; p++) {
        hist_kernel<<<dim3(256, NB), 256>>>(p);
        scan_kernel<<<NB, 32>>>(p);
    }
    sel1_kernel<<<dim3(64, NB), 256>>>(out);
    sel3_kernel<<<dim3(64, NB), 256>>>(out);
    sel4_kernel<<<1, 32>>>(out);
}

// round 16
// speedup vs baseline: 1.1221x; 1.0065x over previous
#include <cuda_runtime.h>
#include <math.h>

#define IMG_H 512
#define IMG_W 512
#define NB    8
#define NC    3
#define HID   64
#define NPIX  (IMG_H*IMG_W)
#define KTOP  26214
#define OUT_XOUT (NB*NC*NPIX)
#define PLANE NPIX
#define BSTRIDE (NC*NPIX)

#define TW 32
#define TH 16
#define HS_W 34
#define HROWS 18
#define PP2 1300          /* floats per icPair plane (648 pairs = 1296, pad to 1300) */

/* blob layout (floats) */
#define OFF_W1 0          /* [27 tap][64 oc]                          1728 */
#define OFF_W2 1728       /* [32 icPair][9 tap][3 o][2 ic-halves]     1728 */
#define OFF_B1 3456       /* 64 */
#define OFF_B2 3520       /* 4  */
#define OFF_CW 3524       /* 12 */
#define OFF_CB 3536       /* 4  */
#define BLOB_FLOATS 3540
/* smem layout */
#define SM_COL 3540       /* 4 */
#define SM_X   3544       /* 3*20*36 = 2160 */
#define SM_H   5704       /* 32*1300 = 41600 (conv2 partials alias after sync) */
#define SMEM_FLOATS 47304
#define SMEM_BYTES (SMEM_FLOATS*4)

typedef unsigned long long ull;

__device__ float    g_blob[BLOB_FLOATS];
__device__ float    g_pmean[24*8];
__device__ float    g_color[24];
__device__ float    g_m[NB*NPIX];
__device__ float    g_bright[NB*NPIX];
__device__ unsigned g_hist[4][NB][256];
__device__ unsigned g_prefix[NB];
__device__ unsigned g_remk[NB];
__device__ float    g_gt[NB][64][3];
__device__ unsigned g_eqcB[NB][64];
__device__ float    g_eqsB[NB][64][3];

__device__ __forceinline__ ull pk2(float a, float b) {
    ull r; asm("mov.b64 %0,{%1,%2};" : "=l"(r) : "f"(a), "f"(b)); return r;
}
__device__ __forceinline__ ull pkd(float a) { return pk2(a, a); }
__device__ __forceinline__ void upk(ull v, float& lo, float& hi) {
    asm("mov.b64 {%0,%1},%2;" : "=f"(lo), "=f"(hi) : "l"(v));
}
__device__ __forceinline__ ull f2(ull a, ull b, ull c) {
    ull d; asm("fma.rn.f32x2 %0,%1,%2,%3;" : "=l"(d) : "l"(a), "l"(b), "l"(c)); return d;
}
__device__ __forceinline__ float sigm(float v) { return 1.f / (1.f + expf(-v)); }

/* ---------------- prep ---------------- */
__global__ void prep_kernel(const float* __restrict__ w1, const float* __restrict__ b1,
                            const float* __restrict__ w2, const float* __restrict__ b2,
                            const float* __restrict__ cw, const float* __restrict__ cb) {
    int tid = threadIdx.x;
    for (int i = tid; i < 1728; i += 256) {           /* w1: [oc][27] -> [tap][oc] */
        int t = i >> 6, oc = i & 63;
        g_blob[OFF_W1 + t*64 + oc] = w1[oc*27 + t];
    }
    for (int i = tid; i < 1728; i += 256) {           /* w2: [o][ic][9] -> [icPair][tap][o][2] */
        int ip = i / 54, r = i % 54, t = r / 6, o = (r % 6) >> 1, k = r & 1;
        g_blob[OFF_W2 + i] = w2[o*576 + (2*ip + k)*9 + t];
    }
    for (int i = tid; i < 64; i += 256) g_blob[OFF_B1 + i] = b1[i];
    if (tid < 4)  g_blob[OFF_B2 + tid] = (tid < 3) ? b2[tid] : 0.f;
    if (tid < 12) g_blob[OFF_CW + tid] = cw[tid];
    if (tid < 4)  g_blob[OFF_CB + tid] = cb[tid];
    unsigned* hz = &g_hist[0][0][0];
    for (int i = tid; i < 4*NB*256; i += 256) hz[i] = 0u;
    if (tid < NB) { g_prefix[tid] = 0u; g_remk[tid] = KTOP; }
}

/* ---------------- mean / color ---------------- */
__device__ float block_reduce256(float v, float* sbuf) {
    int tid = threadIdx.x;
    sbuf[tid] = v; __syncthreads();
    for (int s = 128; s > 0; s >>= 1) {
        if (tid < s) sbuf[tid] += sbuf[tid + s];
        __syncthreads();
    }
    float r = sbuf[0]; __syncthreads();
    return r;
}

__global__ void meanA_kernel(const float* __restrict__ x) {
    __shared__ float sbuf[256];
    int chunk = blockIdx.x, bc = blockIdx.y, tid = threadIdx.x;
    int base = bc * NPIX + chunk * 32768;
    float s = 0.f;
    for (int i = tid; i < 32768; i += 256) s += x[base + i];
    float r = block_reduce256(s, sbuf);
    if (tid == 0) g_pmean[bc*8 + chunk] = r;
}

__global__ void meanB_kernel(const float* __restrict__ color_w, const float* __restrict__ color_b) {
    __shared__ float mm[24];
    int tid = threadIdx.x;
    if (tid < 24) {
        float s = 0.f;
        for (int j = 0; j < 8; j++) s += g_pmean[tid*8 + j];
        mm[tid] = s * (1.f / (float)NPIX);
    }
    __syncthreads();
    if (tid < 24) {
        int b = tid / 3, c = tid % 3;
        float lin = color_b[c];
        for (int j = 0; j < 3; j++) lin += mm[b*3 + j] * color_w[c*3 + j];
        g_color[tid] = sigm(lin);
    }
}

/* ---------------- main fused kernel: 512 threads, 1 block/SM ---------------- */
__global__ void __launch_bounds__(512, 1)
main_kernel(const float* __restrict__ x, float* __restrict__ out) {
    extern __shared__ float sm[];
    int tid = threadIdx.x;
    int b  = blockIdx.z;
    int r0 = blockIdx.y * TH;
    int c0 = blockIdx.x * TW;

    for (int i = tid; i < BLOB_FLOATS; i += 512) sm[i] = g_blob[i];
    if (tid < 3) sm[SM_COL + tid] = g_color[b*3 + tid];

    /* x tile: 3 x 20 x 36, origin (r0-2, c0-2), zero outside image */
    for (int i = tid; i < 3*20*36; i += 512) {
        int ci = i / 720;
        int rr = (i % 720) / 36;
        int cc = i % 36;
        int gr = r0 - 2 + rr, gc = c0 - 2 + cc;
        float v = 0.f;
        if ((unsigned)gr < 512u && (unsigned)gc < 512u)
            v = x[b*BSTRIDE + ci*PLANE + gr*512 + gc];
        sm[SM_X + i] = v;
    }
    __syncthreads();

    /* ---- conv1: warp-per-quad; lane owns oc pair (2*lane, 2*lane+1) ----
       acc u64 IS the channel pair -> stored directly as STS.64, pair-interleaved. */
    {
        int warp = tid >> 5, lane = tid & 31;
        ull w[27];
        #pragma unroll
        for (int t = 0; t < 27; t++)
            w[t] = *(const ull*)&sm[OFF_W1 + t*64 + 2*lane];
        ull bias = *(const ull*)&sm[OFF_B1 + 2*lane];

        for (int quad = warp; quad < 162; quad += 16) {
            int pr = quad / 9, pc0 = (quad % 9) << 2;
            ull acc0 = bias, acc1 = bias, acc2 = bias, acc3 = bias;
            #pragma unroll
            for (int ci = 0; ci < 3; ci++) {
                #pragma unroll
                for (int dr = 0; dr < 3; dr++) {
                    int xbase = SM_X + ci*720 + (pr+dr)*36 + pc0;
                    float4 xa = *(const float4*)&sm[xbase];
                    float2 xb = *(const float2*)&sm[xbase + 4];
                    ull x0 = pkd(xa.x), x1 = pkd(xa.y), x2 = pkd(xa.z);
                    ull x3 = pkd(xa.w), x4 = pkd(xb.x), x5 = pkd(xb.y);
                    const int tb = ci*9 + dr*3;
                    acc0 = f2(x0, w[tb+0], acc0); acc1 = f2(x1, w[tb+0], acc1);
                    acc2 = f2(x2, w[tb+0], acc2); acc3 = f2(x3, w[tb+0], acc3);
                    acc0 = f2(x1, w[tb+1], acc0); acc1 = f2(x2, w[tb+1], acc1);
                    acc2 = f2(x3, w[tb+1], acc2); acc3 = f2(x4, w[tb+1], acc3);
                    acc0 = f2(x2, w[tb+2], acc0); acc1 = f2(x3, w[tb+2], acc1);
                    acc2 = f2(x4, w[tb+2], acc2); acc3 = f2(x5, w[tb+2], acc3);
                }
            }
            int gr = r0 - 1 + pr;
            bool rok = ((unsigned)gr < 512u);
            ull av[4]; av[0]=acc0; av[1]=acc1; av[2]=acc2; av[3]=acc3;
            #pragma unroll
            for (int j = 0; j < 4; j++) {
                int pc = pc0 + j;
                bool ok = rok && (pc < HS_W) && ((unsigned)(c0 - 1 + pc) < 512u);
                float lo, hi; upk(av[j], lo, hi);
                ull pair = ok ? pk2(fmaxf(lo, 0.f), fmaxf(hi, 0.f)) : 0ull;
                *(ull*)&sm[SM_H + lane*PP2 + (pr*36 + pc)*2] = pair;
            }
        }
    }
    __syncthreads();

    /* ---- conv2: unit = 8 pixels x 3 outs x 4 icPairs; pair dim = input channels ----
       64 pixel-octs x 8 groups = 512 threads; zero packs. */
    ull a[8][3];
    int grp = tid >> 6;            /* 0..7 : icPair group */
    int oct = tid & 63;            /* pixel oct */
    {
        int py  = oct >> 2;        /* 0..15 */
        int px0 = (oct & 3) << 3;  /* 0,8,16,24 */
        #pragma unroll
        for (int p = 0; p < 8; p++) { a[p][0] = 0ull; a[p][1] = 0ull; a[p][2] = 0ull; }

        int ip0 = grp * 4;
        for (int ip = ip0; ip < ip0 + 4; ip++) {
            const float* hb = &sm[SM_H + ip*PP2];
            const float* wb = &sm[OFF_W2 + ip*54];
            #pragma unroll
            for (int dr = 0; dr < 3; dr++) {
                const ull* hp = (const ull*)&hb[((py+dr)*36 + px0)*2];
                ull h[10];
                #pragma unroll
                for (int j = 0; j < 10; j++) h[j] = hp[j];
                const ull* wrow = (const ull*)&wb[dr*18];
                #pragma unroll
                for (int dc = 0; dc < 3; dc++) {
                    ull w0 = wrow[dc*3+0], w1 = wrow[dc*3+1], w2 = wrow[dc*3+2];
                    #pragma unroll
                    for (int p = 0; p < 8; p++) {
                        ull hv = h[p + dc];
                        a[p][0] = f2(hv, w0, a[p][0]);
                        a[p][1] = f2(hv, w1, a[p][1]);
                        a[p][2] = f2(hv, w2, a[p][2]);
                    }
                }
            }
        }
    }
    __syncthreads();   /* all H reads done; RED aliases H region */
    {
        /* fold (lo+hi) = sum over the ic pair; write 24 scalars */
        float* rp = &sm[SM_H + (oct*8 + grp)*24];
        #pragma unroll
        for (int o = 0; o < 3; o++) {
            #pragma unroll
            for (int p = 0; p < 8; p++) {
                float lo, hi; upk(a[p][o], lo, hi);
                rp[o*8 + p] = lo + hi;
            }
        }
    }
    __syncthreads();

    /* ---- finalize: sum partials, sigmoid + color + 1x1 + x_out ---- */
    {
        int py = tid >> 5, px = tid & 31;
        int oc2 = py*4 + (px >> 3), j = px & 7;
        float s0 = sm[OFF_B2], s1 = sm[OFF_B2+1], s2 = sm[OFF_B2+2];
        #pragma unroll
        for (int g = 0; g < 8; g++) {
            const float* rp = &sm[SM_H + (oc2*8 + g)*24];
            s0 += rp[j]; s1 += rp[8 + j]; s2 += rp[16 + j];
        }
        float ih0 = sigm(s0) * sm[SM_COL + 0];
        float ih1 = sigm(s1) * sm[SM_COL + 1];
        float ih2 = sigm(s2) * sm[SM_COL + 2];
        const float* cw = &sm[OFF_CW];
        const float* cb = &sm[OFF_CB];
        float K = cb[0] + cw[0]*ih0 + cw[1]*ih1 + cw[2]*ih2;
        int pix = (r0 + py)*512 + (c0 + px);
        float mx = -1e30f;
        #pragma unroll
        for (int c = 0; c < 3; c++) {
            float Bt = cb[1+c] + cw[(1+c)*3+0]*ih0 + cw[(1+c)*3+1]*ih1 + cw[(1+c)*3+2]*ih2;
            float xv = sm[SM_X + c*720 + (py+2)*36 + (px+2)];
            float xo = K*xv - Bt + xv;
            out[b*BSTRIDE + c*PLANE + pix] = xo;
            mx = fmaxf(mx, xo);
        }
        g_m[b*NPIX + pix] = mx;
    }
}

/* ---------------- bright (reflect pad, 3x3) + fused radix pass-0 hist ---------------- */
__global__ void brighthist_kernel() {
    __shared__ unsigned h[256];
    int b = blockIdx.y, tid = threadIdx.x;
    h[tid] = 0; __syncthreads();
    const float* m = &g_m[b*NPIX];
    int base = blockIdx.x*2048;
    #pragma unroll
    for (int k = 0; k < 8; k++) {
        int p = base + k*256 + tid;
        int r = p >> 9, c = p & 511;
        float acc = 0.f;
        #pragma unroll
        for (int dr = 0; dr < 3; dr++) {
            int rr = r + dr - 1; rr = rr < 0 ? 1 : (rr > 511 ? 510 : rr);
            #pragma unroll
            for (int dc = 0; dc < 3; dc++) {
                int cc = c + dc - 1; cc = cc < 0 ? 1 : (cc > 511 ? 510 : cc);
                float w = (dr == 1 && dc == 1) ? 1.0f : (1.f/9.f);
                acc += w * m[rr*512 + cc];
            }
        }
        float bv = fmaxf(acc, 0.f);
        g_bright[b*NPIX + p] = bv;
        atomicAdd(&h[__float_as_uint(bv) >> 24], 1u);
    }
    __syncthreads();
    if (h[tid]) atomicAdd(&g_hist[0][b][tid], h[tid]);
}

/* ---------------- radix select (passes 1-3) ---------------- */
__global__ void hist_kernel(int pass) {
    __shared__ unsigned h[256];
    int b = blockIdx.y, tid = threadIdx.x;
    h[tid] = 0; __syncthreads();
    unsigned pref = g_prefix[b];
    int shift = 24 - 8*pass;
    int base = b*NPIX + blockIdx.x*1024;
    for (int i = tid; i < 1024; i += 256) {
        unsigned u = __float_as_uint(g_bright[base + i]);
        if ((u >> (shift + 8)) == pref) atomicAdd(&h[(u >> shift) & 255], 1u);
    }
    __syncthreads();
    if (h[tid]) atomicAdd(&g_hist[pass][b][tid], h[tid]);
}

__global__ void scan_kernel(int pass) {
    int b = blockIdx.x;
    if (threadIdx.x == 0) {
        unsigned remk = g_remk[b], cum = 0, pref = g_prefix[b], sel = 0;
        for (int bin = 255; bin >= 0; bin--) {
            unsigned c = g_hist[pass][b][bin];
            if (cum + c >= remk) { sel = (unsigned)bin; break; }
            cum += c;
        }
        g_prefix[b] = (pref << 8) | sel;
        g_remk[b] = remk - cum;
    }
}

__global__ void sel1_kernel(const float* __restrict__ outp) {
    __shared__ float s0[256], s1[256], s2[256];
    __shared__ unsigned sc[256];
    int b = blockIdx.y, blk = blockIdx.x, tid = threadIdx.x;
    unsigned T = g_prefix[b];
    const float* br  = &g_bright[b*NPIX];
    const float* img = outp + b*BSTRIDE;
    int base = blk*4096;
    float a0 = 0, a1 = 0, a2 = 0; unsigned ec = 0;
    for (int i = tid; i < 4096; i += 256) {
        int p = base + i;
        unsigned u = __float_as_uint(br[p]);
        if (u > T) { a0 += img[p*3]; a1 += img[p*3+1]; a2 += img[p*3+2]; }
        else if (u == T) ec++;
    }
    s0[tid]=a0; s1[tid]=a1; s2[tid]=a2; sc[tid]=ec; __syncthreads();
    for (int s = 128; s > 0; s >>= 1) {
        if (tid < s) { s0[tid]+=s0[tid+s]; s1[tid]+=s1[tid+s]; s2[tid]+=s2[tid+s]; sc[tid]+=sc[tid+s]; }
        __syncthreads();
    }
    if (tid == 0) {
        g_gt[b][blk][0]=s0[0]; g_gt[b][blk][1]=s1[0]; g_gt[b][blk][2]=s2[0];
        g_eqcB[b][blk]=sc[0];
    }
}

__global__ void sel3_kernel(const float* __restrict__ outp) {
    __shared__ unsigned scnt[256];
    __shared__ unsigned eqc[64];
    __shared__ unsigned startsh;
    __shared__ float s0[256], s1[256], s2[256];
    int b = blockIdx.y, blk = blockIdx.x, tid = threadIdx.x;
    unsigned T = g_prefix[b], remk = g_remk[b];
    const float* br  = &g_bright[b*NPIX];
    const float* img = outp + b*BSTRIDE;
    if (tid < 64) eqc[tid] = g_eqcB[b][tid];
    int start = blk*4096 + tid*16;
    unsigned cnt = 0;
    for (int j = 0; j < 16; j++) if (__float_as_uint(br[start+j]) == T) cnt++;
    scnt[tid] = cnt; __syncthreads();
    if (tid == 0) {
        unsigned run = 0;
        for (int i = 0; i < blk; i++) run += eqc[i];
        startsh = run;
        run = 0;
        for (int i = 0; i < 256; i++) { unsigned c = scnt[i]; scnt[i] = run; run += c; }
    }
    __syncthreads();
    unsigned rank = startsh + scnt[tid];
    float a0 = 0, a1 = 0, a2 = 0;
    for (int j = 0; j < 16; j++) {
        int p = start + j;
        if (__float_as_uint(br[p]) == T) {
            if (rank < remk) { a0 += img[p*3]; a1 += img[p*3+1]; a2 += img[p*3+2]; }
            rank++;
        }
    }
    s0[tid]=a0; s1[tid]=a1; s2[tid]=a2; __syncthreads();
    for (int s = 128; s > 0; s >>= 1) {
        if (tid < s) { s0[tid]+=s0[tid+s]; s1[tid]+=s1[tid+s]; s2[tid]+=s2[tid+s]; }
        __syncthreads();
    }
    if (tid == 0) { g_eqsB[b][blk][0]=s0[0]; g_eqsB[b][blk][1]=s1[0]; g_eqsB[b][blk][2]=s2[0]; }
}

__global__ void sel4_kernel(float* __restrict__ outp) {
    int tid = threadIdx.x;
    if (tid < 24) {
        int b = tid / 3, c = tid % 3;
        float s = 0.f;
        for (int i = 0; i < 64; i++) s += g_gt[b][i][c] + g_eqsB[b][i][c];
        outp[OUT_XOUT + tid] = s * (1.f / (float)KTOP);
    }
}

/* ---------------- launch ---------------- */
extern "C" void kernel_launch(void* const* d_in, const int* in_sizes, int n_in,
                              void* d_out, int out_size) {
    const float* x   = (const float*)d_in[0];
    const float* w1  = (const float*)d_in[1];
    const float* b1  = (const float*)d_in[2];
    const float* w2  = (const float*)d_in[3];
    const float* b2  = (const float*)d_in[4];
    const float* cwm = (const float*)d_in[5];   /* color_w (3x3) */
    const float* cbm = (const float*)d_in[6];   /* color_b (3)   */
    const float* cw  = (const float*)d_in[7];   /* conv_w (4x3)  */
    const float* cb  = (const float*)d_in[8];   /* conv_b (4)    */
    float* out = (float*)d_out;

    cudaFuncSetAttribute(main_kernel, cudaFuncAttributeMaxDynamicSharedMemorySize, SMEM_BYTES);

    prep_kernel<<<1, 256>>>(w1, b1, w2, b2, cw, cb);
    meanA_kernel<<<dim3(8, 24), 256>>>(x);
    meanB_kernel<<<1, 32>>>(cwm, cbm);
    main_kernel<<<dim3(IMG_W/TW, IMG_H/TH, NB), 512, SMEM_BYTES>>>(x, out);
    brighthist_kernel<<<dim3(NPIX/2048, NB), 256>>>();
    scan_kernel<<<NB, 32>>>(0);
    for (int p = 1; p < 4; p++) {
        hist_kernel<<<dim3(256, NB), 256>>>(p);
        scan_kernel<<<NB, 32>>>(p);
    }
    sel1_kernel<<<dim3(64, NB), 256>>>(out);
    sel3_kernel<<<dim3(64, NB), 256>>>(out);
    sel4_kernel<<<1, 32>>>(out);
}

// round 17
// speedup vs baseline: 1.1349x; 1.0114x over previous
#include <cuda_runtime.h>
#include <math.h>

#define IMG_H 512
#define IMG_W 512
#define NB    8
#define NC    3
#define HID   64
#define NPIX  (IMG_H*IMG_W)
#define KTOP  26214
#define OUT_XOUT (NB*NC*NPIX)
#define PLANE NPIX
#define BSTRIDE (NC*NPIX)

#define TW 32
#define TH 16
#define HS_W 34
#define HROWS 18
#define ROWU 38           /* h row stride in u64 (pixel pairs); 38%16=6 -> conflict-free conv2 loads */
#define PP2  1380         /* floats per icPair plane; u64 stride 690 (even, %16==2) */

/* blob layout (floats) */
#define OFF_W1 0          /* [27 tap][64 oc]                          1728 */
#define OFF_W2 1728       /* [32 icPair][9 tap][3 o][2 ic-halves]     1728 */
#define OFF_B1 3456       /* 64 */
#define OFF_B2 3520       /* 4  */
#define OFF_CW 3524       /* 12 */
#define OFF_CB 3536       /* 4  */
#define BLOB_FLOATS 3540
/* smem layout */
#define SM_COL 3540       /* 4 */
#define SM_X   3544       /* 3*20*36 = 2160 */
#define SM_H   5704       /* 32*1380 = 44160 (conv2 partials alias after sync) */
#define SMEM_FLOATS 49864
#define SMEM_BYTES (SMEM_FLOATS*4)

typedef unsigned long long ull;

__device__ float    g_blob[BLOB_FLOATS];
__device__ float    g_pmean[24*8];
__device__ float    g_color[24];
__device__ float    g_m[NB*NPIX];
__device__ float    g_bright[NB*NPIX];
__device__ unsigned g_hist[4][NB][256];
__device__ unsigned g_prefix[NB];
__device__ unsigned g_remk[NB];
__device__ float    g_gt[NB][64][3];
__device__ unsigned g_eqcB[NB][64];
__device__ float    g_eqsB[NB][64][3];

__device__ __forceinline__ ull pk2(float a, float b) {
    ull r; asm("mov.b64 %0,{%1,%2};" : "=l"(r) : "f"(a), "f"(b)); return r;
}
__device__ __forceinline__ ull pkd(float a) { return pk2(a, a); }
__device__ __forceinline__ void upk(ull v, float& lo, float& hi) {
    asm("mov.b64 {%0,%1},%2;" : "=f"(lo), "=f"(hi) : "l"(v));
}
__device__ __forceinline__ ull f2(ull a, ull b, ull c) {
    ull d; asm("fma.rn.f32x2 %0,%1,%2,%3;" : "=l"(d) : "l"(a), "l"(b), "l"(c)); return d;
}
__device__ __forceinline__ float sigm(float v) { return 1.f / (1.f + expf(-v)); }

/* ---------------- prep ---------------- */
__global__ void prep_kernel(const float* __restrict__ w1, const float* __restrict__ b1,
                            const float* __restrict__ w2, const float* __restrict__ b2,
                            const float* __restrict__ cw, const float* __restrict__ cb) {
    int tid = threadIdx.x;
    for (int i = tid; i < 1728; i += 256) {           /* w1: [oc][27] -> [tap][oc] */
        int t = i >> 6, oc = i & 63;
        g_blob[OFF_W1 + t*64 + oc] = w1[oc*27 + t];
    }
    for (int i = tid; i < 1728; i += 256) {           /* w2: [o][ic][9] -> [icPair][tap][o][2] */
        int ip = i / 54, r = i % 54, t = r / 6, o = (r % 6) >> 1, k = r & 1;
        g_blob[OFF_W2 + i] = w2[o*576 + (2*ip + k)*9 + t];
    }
    for (int i = tid; i < 64; i += 256) g_blob[OFF_B1 + i] = b1[i];
    if (tid < 4)  g_blob[OFF_B2 + tid] = (tid < 3) ? b2[tid] : 0.f;
    if (tid < 12) g_blob[OFF_CW + tid] = cw[tid];
    if (tid < 4)  g_blob[OFF_CB + tid] = cb[tid];
    unsigned* hz = &g_hist[0][0][0];
    for (int i = tid; i < 4*NB*256; i += 256) hz[i] = 0u;
    if (tid < NB) { g_prefix[tid] = 0u; g_remk[tid] = KTOP; }
}

/* ---------------- mean / color ---------------- */
__device__ float block_reduce256(float v, float* sbuf) {
    int tid = threadIdx.x;
    sbuf[tid] = v; __syncthreads();
    for (int s = 128; s > 0; s >>= 1) {
        if (tid < s) sbuf[tid] += sbuf[tid + s];
        __syncthreads();
    }
    float r = sbuf[0]; __syncthreads();
    return r;
}

__global__ void meanA_kernel(const float* __restrict__ x) {
    __shared__ float sbuf[256];
    int chunk = blockIdx.x, bc = blockIdx.y, tid = threadIdx.x;
    int base = bc * NPIX + chunk * 32768;
    float s = 0.f;
    for (int i = tid; i < 32768; i += 256) s += x[base + i];
    float r = block_reduce256(s, sbuf);
    if (tid == 0) g_pmean[bc*8 + chunk] = r;
}

__global__ void meanB_kernel(const float* __restrict__ color_w, const float* __restrict__ color_b) {
    __shared__ float mm[24];
    int tid = threadIdx.x;
    if (tid < 24) {
        float s = 0.f;
        for (int j = 0; j < 8; j++) s += g_pmean[tid*8 + j];
        mm[tid] = s * (1.f / (float)NPIX);
    }
    __syncthreads();
    if (tid < 24) {
        int b = tid / 3, c = tid % 3;
        float lin = color_b[c];
        for (int j = 0; j < 3; j++) lin += mm[b*3 + j] * color_w[c*3 + j];
        g_color[tid] = sigm(lin);
    }
}

/* ---------------- main fused kernel: 512 threads, 1 block/SM ---------------- */
__global__ void __launch_bounds__(512, 1)
main_kernel(const float* __restrict__ x, float* __restrict__ out) {
    extern __shared__ float sm[];
    int tid = threadIdx.x;
    int b  = blockIdx.z;
    int r0 = blockIdx.y * TH;
    int c0 = blockIdx.x * TW;

    for (int i = tid; i < BLOB_FLOATS; i += 512) sm[i] = g_blob[i];
    if (tid < 3) sm[SM_COL + tid] = g_color[b*3 + tid];

    /* x tile: 3 x 20 x 36, origin (r0-2, c0-2), zero outside image */
    for (int i = tid; i < 3*20*36; i += 512) {
        int ci = i / 720;
        int rr = (i % 720) / 36;
        int cc = i % 36;
        int gr = r0 - 2 + rr, gc = c0 - 2 + cc;
        float v = 0.f;
        if ((unsigned)gr < 512u && (unsigned)gc < 512u)
            v = x[b*BSTRIDE + ci*PLANE + gr*512 + gc];
        sm[SM_X + i] = v;
    }
    __syncthreads();

    /* ---- conv1: warp-per-quad; lane owns oc pair (2*lane, 2*lane+1) ----
       acc u64 IS the channel pair -> stored directly as STS.64, pair-interleaved. */
    {
        int warp = tid >> 5, lane = tid & 31;
        ull w[27];
        #pragma unroll
        for (int t = 0; t < 27; t++)
            w[t] = *(const ull*)&sm[OFF_W1 + t*64 + 2*lane];
        ull bias = *(const ull*)&sm[OFF_B1 + 2*lane];

        for (int quad = warp; quad < 162; quad += 16) {
            int pr = quad / 9, pc0 = (quad % 9) << 2;
            ull acc0 = bias, acc1 = bias, acc2 = bias, acc3 = bias;
            #pragma unroll
            for (int ci = 0; ci < 3; ci++) {
                #pragma unroll
                for (int dr = 0; dr < 3; dr++) {
                    int xbase = SM_X + ci*720 + (pr+dr)*36 + pc0;
                    float4 xa = *(const float4*)&sm[xbase];
                    float2 xb = *(const float2*)&sm[xbase + 4];
                    ull x0 = pkd(xa.x), x1 = pkd(xa.y), x2 = pkd(xa.z);
                    ull x3 = pkd(xa.w), x4 = pkd(xb.x), x5 = pkd(xb.y);
                    const int tb = ci*9 + dr*3;
                    acc0 = f2(x0, w[tb+0], acc0); acc1 = f2(x1, w[tb+0], acc1);
                    acc2 = f2(x2, w[tb+0], acc2); acc3 = f2(x3, w[tb+0], acc3);
                    acc0 = f2(x1, w[tb+1], acc0); acc1 = f2(x2, w[tb+1], acc1);
                    acc2 = f2(x3, w[tb+1], acc2); acc3 = f2(x4, w[tb+1], acc3);
                    acc0 = f2(x2, w[tb+2], acc0); acc1 = f2(x3, w[tb+2], acc1);
                    acc2 = f2(x4, w[tb+2], acc2); acc3 = f2(x5, w[tb+2], acc3);
                }
            }
            int gr = r0 - 1 + pr;
            bool rok = ((unsigned)gr < 512u);
            ull av[4]; av[0]=acc0; av[1]=acc1; av[2]=acc2; av[3]=acc3;
            #pragma unroll
            for (int j = 0; j < 4; j++) {
                int pc = pc0 + j;
                bool ok = rok && (pc < HS_W) && ((unsigned)(c0 - 1 + pc) < 512u);
                float lo, hi; upk(av[j], lo, hi);
                ull pair = ok ? pk2(fmaxf(lo, 0.f), fmaxf(hi, 0.f)) : 0ull;
                *(ull*)&sm[SM_H + lane*PP2 + (pr*ROWU + pc)*2] = pair;
            }
        }
    }
    __syncthreads();

    /* ---- conv2: unit = 8 pixels x 3 outs x 4 icPairs ----
       mapping py = oct&15, pxg = oct>>4 -> each 8-lane LDS.128 phase has 8
       distinct py (stride 38 u64, %16=6) -> conflict-free h loads. */
    ull a[8][3];
    int grp = tid >> 6;            /* 0..7 : icPair group */
    int oct = tid & 63;            /* pixel oct */
    {
        int py  = oct & 15;        /* 0..15 */
        int px0 = (oct >> 4) << 3; /* 0,8,16,24 */
        #pragma unroll
        for (int p = 0; p < 8; p++) { a[p][0] = 0ull; a[p][1] = 0ull; a[p][2] = 0ull; }

        int ip0 = grp * 4;
        for (int ip = ip0; ip < ip0 + 4; ip++) {
            const float* hb = &sm[SM_H + ip*PP2];
            const float* wb = &sm[OFF_W2 + ip*54];
            #pragma unroll
            for (int dr = 0; dr < 3; dr++) {
                const ull* hp = (const ull*)&hb[((py+dr)*ROWU + px0)*2];
                ull h[10];
                #pragma unroll
                for (int j = 0; j < 10; j++) h[j] = hp[j];
                const ull* wrow = (const ull*)&wb[dr*18];
                #pragma unroll
                for (int dc = 0; dc < 3; dc++) {
                    ull w0 = wrow[dc*3+0], w1 = wrow[dc*3+1], w2 = wrow[dc*3+2];
                    #pragma unroll
                    for (int p = 0; p < 8; p++) {
                        ull hv = h[p + dc];
                        a[p][0] = f2(hv, w0, a[p][0]);
                        a[p][1] = f2(hv, w1, a[p][1]);
                        a[p][2] = f2(hv, w2, a[p][2]);
                    }
                }
            }
        }
    }
    __syncthreads();   /* all H reads done; RED aliases H region */
    {
        /* fold (lo+hi) = sum over the ic pair; write 24 scalars */
        float* rp = &sm[SM_H + (oct*8 + grp)*24];
        #pragma unroll
        for (int o = 0; o < 3; o++) {
            #pragma unroll
            for (int p = 0; p < 8; p++) {
                float lo, hi; upk(a[p][o], lo, hi);
                rp[o*8 + p] = lo + hi;
            }
        }
    }
    __syncthreads();

    /* ---- finalize: sum partials, sigmoid + color + 1x1 + x_out ---- */
    {
        int py = tid >> 5, px = tid & 31;
        int oc2 = ((px >> 3) << 4) + py;   /* oct of this pixel under new mapping */
        int j = px & 7;
        float s0 = sm[OFF_B2], s1 = sm[OFF_B2+1], s2 = sm[OFF_B2+2];
        #pragma unroll
        for (int g = 0; g < 8; g++) {
            const float* rp = &sm[SM_H + (oc2*8 + g)*24];
            s0 += rp[j]; s1 += rp[8 + j]; s2 += rp[16 + j];
        }
        float ih0 = sigm(s0) * sm[SM_COL + 0];
        float ih1 = sigm(s1) * sm[SM_COL + 1];
        float ih2 = sigm(s2) * sm[SM_COL + 2];
        const float* cw = &sm[OFF_CW];
        const float* cb = &sm[OFF_CB];
        float K = cb[0] + cw[0]*ih0 + cw[1]*ih1 + cw[2]*ih2;
        int pix = (r0 + py)*512 + (c0 + px);
        float mx = -1e30f;
        #pragma unroll
        for (int c = 0; c < 3; c++) {
            float Bt = cb[1+c] + cw[(1+c)*3+0]*ih0 + cw[(1+c)*3+1]*ih1 + cw[(1+c)*3+2]*ih2;
            float xv = sm[SM_X + c*720 + (py+2)*36 + (px+2)];
            float xo = K*xv - Bt + xv;
            out[b*BSTRIDE + c*PLANE + pix] = xo;
            mx = fmaxf(mx, xo);
        }
        g_m[b*NPIX + pix] = mx;
    }
}

/* ---------------- bright (reflect pad, 3x3) + fused radix pass-0 hist ---------------- */
__global__ void brighthist_kernel() {
    __shared__ unsigned h[256];
    int b = blockIdx.y, tid = threadIdx.x;
    h[tid] = 0; __syncthreads();
    const float* m = &g_m[b*NPIX];
    int base = blockIdx.x*2048;
    #pragma unroll
    for (int k = 0; k < 8; k++) {
        int p = base + k*256 + tid;
        int r = p >> 9, c = p & 511;
        float acc = 0.f;
        #pragma unroll
        for (int dr = 0; dr < 3; dr++) {
            int rr = r + dr - 1; rr = rr < 0 ? 1 : (rr > 511 ? 510 : rr);
            #pragma unroll
            for (int dc = 0; dc < 3; dc++) {
                int cc = c + dc - 1; cc = cc < 0 ? 1 : (cc > 511 ? 510 : cc);
                float w = (dr == 1 && dc == 1) ? 1.0f : (1.f/9.f);
                acc += w * m[rr*512 + cc];
            }
        }
        float bv = fmaxf(acc, 0.f);
        g_bright[b*NPIX + p] = bv;
        atomicAdd(&h[__float_as_uint(bv) >> 24], 1u);
    }
    __syncthreads();
    if (h[tid]) atomicAdd(&g_hist[0][b][tid], h[tid]);
}

/* ---------------- radix select (passes 1-3) ---------------- */
__global__ void hist_kernel(int pass) {
    __shared__ unsigned h[256];
    int b = blockIdx.y, tid = threadIdx.x;
    h[tid] = 0; __syncthreads();
    unsigned pref = g_prefix[b];
    int shift = 24 - 8*pass;
    int base = b*NPIX + blockIdx.x*1024;
    for (int i = tid; i < 1024; i += 256) {
        unsigned u = __float_as_uint(g_bright[base + i]);
        if ((u >> (shift + 8)) == pref) atomicAdd(&h[(u >> shift) & 255], 1u);
    }
    __syncthreads();
    if (h[tid]) atomicAdd(&g_hist[pass][b][tid], h[tid]);
}

__global__ void scan_kernel(int pass) {
    int b = blockIdx.x;
    if (threadIdx.x == 0) {
        unsigned remk = g_remk[b], cum = 0, pref = g_prefix[b], sel = 0;
        for (int bin = 255; bin >= 0; bin--) {
            unsigned c = g_hist[pass][b][bin];
            if (cum + c >= remk) { sel = (unsigned)bin; break; }
            cum += c;
        }
        g_prefix[b] = (pref << 8) | sel;
        g_remk[b] = remk - cum;
    }
}

__global__ void sel1_kernel(const float* __restrict__ outp) {
    __shared__ float s0[256], s1[256], s2[256];
    __shared__ unsigned sc[256];
    int b = blockIdx.y, blk = blockIdx.x, tid = threadIdx.x;
    unsigned T = g_prefix[b];
    const float* br  = &g_bright[b*NPIX];
    const float* img = outp + b*BSTRIDE;
    int base = blk*4096;
    float a0 = 0, a1 = 0, a2 = 0; unsigned ec = 0;
    for (int i = tid; i < 4096; i += 256) {
        int p = base + i;
        unsigned u = __float_as_uint(br[p]);
        if (u > T) { a0 += img[p*3]; a1 += img[p*3+1]; a2 += img[p*3+2]; }
        else if (u == T) ec++;
    }
    s0[tid]=a0; s1[tid]=a1; s2[tid]=a2; sc[tid]=ec; __syncthreads();
    for (int s = 128; s > 0; s >>= 1) {
        if (tid < s) { s0[tid]+=s0[tid+s]; s1[tid]+=s1[tid+s]; s2[tid]+=s2[tid+s]; sc[tid]+=sc[tid+s]; }
        __syncthreads();
    }
    if (tid == 0) {
        g_gt[b][blk][0]=s0[0]; g_gt[b][blk][1]=s1[0]; g_gt[b][blk][2]=s2[0];
        g_eqcB[b][blk]=sc[0];
    }
}

__global__ void sel3_kernel(const float* __restrict__ outp) {
    __shared__ unsigned scnt[256];
    __shared__ unsigned eqc[64];
    __shared__ unsigned startsh;
    __shared__ float s0[256], s1[256], s2[256];
    int b = blockIdx.y, blk = blockIdx.x, tid = threadIdx.x;
    unsigned T = g_prefix[b], remk = g_remk[b];
    const float* br  = &g_bright[b*NPIX];
    const float* img = outp + b*BSTRIDE;
    if (tid < 64) eqc[tid] = g_eqcB[b][tid];
    int start = blk*4096 + tid*16;
    unsigned cnt = 0;
    for (int j = 0; j < 16; j++) if (__float_as_uint(br[start+j]) == T) cnt++;
    scnt[tid] = cnt; __syncthreads();
    if (tid == 0) {
        unsigned run = 0;
        for (int i = 0; i < blk; i++) run += eqc[i];
        startsh = run;
        run = 0;
        for (int i = 0; i < 256; i++) { unsigned c = scnt[i]; scnt[i] = run; run += c; }
    }
    __syncthreads();
    unsigned rank = startsh + scnt[tid];
    float a0 = 0, a1 = 0, a2 = 0;
    for (int j = 0; j < 16; j++) {
        int p = start + j;
        if (__float_as_uint(br[p]) == T) {
            if (rank < remk) { a0 += img[p*3]; a1 += img[p*3+1]; a2 += img[p*3+2]; }
            rank++;
        }
    }
    s0[tid]=a0; s1[tid]=a1; s2[tid]=a2; __syncthreads();
    for (int s = 128; s > 0; s >>= 1) {
        if (tid < s) { s0[tid]+=s0[tid+s]; s1[tid]+=s1[tid+s]; s2[tid]+=s2[tid+s]; }
        __syncthreads();
    }
    if (tid == 0) { g_eqsB[b][blk][0]=s0[0]; g_eqsB[b][blk][1]=s1[0]; g_eqsB[b][blk][2]=s2[0]; }
}

__global__ void sel4_kernel(float* __restrict__ outp) {
    int tid = threadIdx.x;
    if (tid < 24) {
        int b = tid / 3, c = tid % 3;
        float s = 0.f;
        for (int i = 0; i < 64; i++) s += g_gt[b][i][c] + g_eqsB[b][i][c];
        outp[OUT_XOUT + tid] = s * (1.f / (float)KTOP);
    }
}

/* ---------------- launch ---------------- */
extern "C" void kernel_launch(void* const* d_in, const int* in_sizes, int n_in,
                              void* d_out, int out_size) {
    const float* x   = (const float*)d_in[0];
    const float* w1  = (const float*)d_in[1];
    const float* b1  = (const float*)d_in[2];
    const float* w2  = (const float*)d_in[3];
    const float* b2  = (const float*)d_in[4];
    const float* cwm = (const float*)d_in[5];   /* color_w (3x3) */
    const float* cbm = (const float*)d_in[6];   /* color_b (3)   */
    const float* cw  = (const float*)d_in[7];   /* conv_w (4x3)  */
    const float* cb  = (const float*)d_in[8];   /* conv_b (4)    */
    float* out = (float*)d_out;

    cudaFuncSetAttribute(main_kernel, cudaFuncAttributeMaxDynamicSharedMemorySize, SMEM_BYTES);

    prep_kernel<<<1, 256>>>(w1, b1, w2, b2, cw, cb);
    meanA_kernel<<<dim3(8, 24), 256>>>(x);
    meanB_kernel<<<1, 32>>>(cwm, cbm);
    main_kernel<<<dim3(IMG_W/TW, IMG_H/TH, NB), 512, SMEM_BYTES>>>(x, out);
    brighthist_kernel<<<dim3(NPIX/2048, NB), 256>>>();
    scan_kernel<<<NB, 32>>>(0);
    for (int p = 1; p < 4; p++) {
        hist_kernel<<<dim3(256, NB), 256>>>(p);
        scan_kernel<<<NB, 32>>>(p);
    }
    sel1_kernel<<<dim3(64, NB), 256>>>(out);
    sel3_kernel<<<dim3(64, NB), 256>>>(out);
    sel4_kernel<<<1, 32>>>(out);
}